// round 6
// baseline (speedup 1.0000x reference)
#include <cuda_runtime.h>
#include <cuda_bf16.h>

// ---------------------------------------------------------------------------
// TransformerV2: conv feature branch + patch-similarity top-5 attention.
// Shapes fixed by the problem: B=1, Cin=64, Cq=32, H=W=96, L=9216, D=32*9=288.
// ---------------------------------------------------------------------------

#define Hh 96
#define Ww 96
#define HW 9216         // 96*96
#define CIN 64
#define CQ  32
#define DQ  288         // CQ*9
#define LQ  9216

typedef unsigned long long ull;

// -------------------------- scratch (static, no allocs) --------------------
__device__ float g_t1  [CIN * HW];     // relu(conv1(x))
__device__ float g_feat[CIN * HW];     // relu(conv2(t1))
__device__ float g_q   [CQ  * HW];
__device__ float g_k   [CQ  * HW];
__device__ float g_Qn  [LQ * DQ];      // normalized query patch vectors [L][288]
__device__ float g_Kn  [LQ * DQ];      // normalized key   patch vectors [L][288]
__device__ float g_xT  [HW * CIN];     // x transposed to [pixel][channel]
__device__ float g_tv  [LQ * 5];       // top5 values  [L][5]
__device__ int   g_ti  [LQ * 5];       // top5 indices [L][5]

// ---------------------------------------------------------------------------
// 3x3 SAME conv, Cin=64 fixed, Cout multiple of 8. Tile 32(w) x 16(h),
// 8 output channels per block. grid (3, 6, Cout/8), block (32, 8).
// ---------------------------------------------------------------------------
__global__ void __launch_bounds__(256) conv3x3_kernel(
    const float* __restrict__ in,   // [64][96][96]
    const float* __restrict__ wgt,  // [Cout][64][3][3]
    const float* __restrict__ bias, // [Cout]
    float* __restrict__ out,        // [Cout][96][96]
    int doRelu)
{
    __shared__ float tin[18][36];
    __shared__ float wsm[64][72];   // [cin][o*9+k] for the 8 outs of this block

    const int tx = threadIdx.x;          // 0..31
    const int ty = threadIdx.y;          // 0..7
    const int tid = ty * 32 + tx;
    const int x0 = blockIdx.x * 32;
    const int y0 = blockIdx.y * 16;
    const int og = blockIdx.z * 8;

    // stage all weights for this output-channel group (4608 floats)
    for (int i = tid; i < 8 * 64 * 9; i += 256) {
        int o   = i / 576;
        int rem = i - o * 576;
        int ci  = rem / 9;
        int k   = rem - ci * 9;
        wsm[ci][o * 9 + k] = wgt[((og + o) * 64 + ci) * 9 + k];
    }

    float acc[8][2];
#pragma unroll
    for (int o = 0; o < 8; o++) { acc[o][0] = 0.f; acc[o][1] = 0.f; }

    for (int ci = 0; ci < 64; ci++) {
        __syncthreads();
        // input tile rows y0-1..y0+16 (18), cols x0-1..x0+32 (34), zero-padded
        for (int i = tid; i < 18 * 34; i += 256) {
            int r = i / 34, c = i - r * 34;
            int gy = y0 - 1 + r, gx = x0 - 1 + c;
            float v = 0.f;
            if (gy >= 0 && gy < Hh && gx >= 0 && gx < Ww)
                v = in[ci * HW + gy * Ww + gx];
            tin[r][c] = v;
        }
        __syncthreads();

        float v[2][9];
#pragma unroll
        for (int rr = 0; rr < 2; rr++) {
            int yl = ty + 8 * rr;
#pragma unroll
            for (int dy = 0; dy < 3; dy++)
#pragma unroll
                for (int dx = 0; dx < 3; dx++)
                    v[rr][dy * 3 + dx] = tin[yl + dy][tx + dx];
        }
#pragma unroll
        for (int o = 0; o < 8; o++) {
            float w9[9];
#pragma unroll
            for (int k = 0; k < 9; k++) w9[k] = wsm[ci][o * 9 + k];
#pragma unroll
            for (int rr = 0; rr < 2; rr++)
#pragma unroll
                for (int k = 0; k < 9; k++)
                    acc[o][rr] = fmaf(v[rr][k], w9[k], acc[o][rr]);
        }
    }

    const int gx = x0 + tx;
#pragma unroll
    for (int o = 0; o < 8; o++) {
        float b = bias[og + o];
#pragma unroll
        for (int rr = 0; rr < 2; rr++) {
            int gy = y0 + ty + 8 * rr;
            float r = acc[o][rr] + b;
            if (doRelu) r = fmaxf(r, 0.f);
            out[(og + o) * HW + gy * Ww + gx] = r;
        }
    }
}

// ---------------------------------------------------------------------------
// Build L2-normalized 3x3 patch vectors: one block per spatial position,
// 288 threads (one per patch element). grid 9216, block 288.
// ---------------------------------------------------------------------------
__global__ void patch_norm_kernel(const float* __restrict__ f,  // [32][96][96]
                                  float* __restrict__ vec)       // [L][288]
{
    const int l = blockIdx.x;
    const int y = l / Ww, x = l - y * Ww;
    const int d = threadIdx.x;          // 0..287
    const int c = d / 9, ij = d - c * 9;
    const int dy = ij / 3 - 1, dx = ij % 3 - 1;
    const int yy = y + dy, xx = x + dx;

    float v = 0.f;
    if (yy >= 0 && yy < Hh && xx >= 0 && xx < Ww)
        v = f[c * HW + yy * Ww + xx];

    __shared__ float red[9];
    __shared__ float nrm;
    float s = v * v;
#pragma unroll
    for (int off = 16; off > 0; off >>= 1)
        s += __shfl_down_sync(0xffffffffu, s, off);
    if ((d & 31) == 0) red[d >> 5] = s;
    __syncthreads();
    if (d == 0) {
        float t = 0.f;
#pragma unroll
        for (int i = 0; i < 9; i++) t += red[i];
        float n = sqrtf(t);
        nrm = fmaxf(n, 1e-12f);
    }
    __syncthreads();
    vec[l * DQ + d] = v / nrm;
}

// ---------------------------------------------------------------------------
// x -> xT  (CHW -> HWC) for coalesced channel gathers in assembly.
// ---------------------------------------------------------------------------
__global__ void transpose_x_kernel(const float* __restrict__ x,
                                   float* __restrict__ xT)
{
    int i = blockIdx.x * 256 + threadIdx.x;
    if (i < CIN * HW) {
        int p = i >> 6, c = i & 63;
        xT[i] = x[c * HW + p];
    }
}

// ---------------------------------------------------------------------------
// Fused similarity GEMM + streaming top-5.
// Per CTA: 64 queries; stream 72 key tiles of 128; 256 threads.
// Micro-tile per thread: 8 keys x 4 queries, accumulated with packed
// fma.rn.f32x2 (FFMA2). Key tile stored value-duplicated in smem so a-frags
// load already packed (broadcast LDS, no per-step packing).
// Top-5 kept per (query, key-quarter) in registers; cross-quarter merge at end
// with jax tie semantics (equal value -> lower index wins).
// grid 144, block 256.
// ---------------------------------------------------------------------------
__device__ __forceinline__ ull fma2(ull a, ull b, ull c) {
    ull d;
    asm("fma.rn.f32x2 %0, %1, %2, %3;" : "=l"(d) : "l"(a), "l"(b), "l"(c));
    return d;
}

__global__ void __launch_bounds__(256, 1) sim_top5_kernel(
    const float* __restrict__ Kn,   // [L][288]
    const float* __restrict__ Qn,   // [L][288]
    float* __restrict__ tvals,      // [L][5]
    int*   __restrict__ tidx)       // [L][5]
{
    __shared__ __align__(16) union SMem {
        struct { float2 A[16][128]; float B[16][64]; } ld;   // 16K + 4K
        float scores[128][66];                               // 33792 B
        struct { float v[64][20]; int id[64][20]; } cand;    // 10240 B
    } sm;

    const int tid = threadIdx.x;
    const int txq = tid & 15;            // query group
    const int tyk = tid >> 4;            // key group
    const int k0 = tyk * 8;
    const int q0 = txq * 4;
    const int qBase = blockIdx.x * 64;

    const int lKey = tid >> 1, lDp = (tid & 1) * 8;      // A-tile loaders
    const int lQ   = tid >> 2, lQdp = (tid & 3) * 4;     // B-tile loaders
    const int qScan = tid & 63, ksScan = (tid >> 6) * 32;

    float v5[5]; int i5[5];
#pragma unroll
    for (int r = 0; r < 5; r++) { v5[r] = -1e30f; i5[r] = 0; }

    const float* aSrc = Kn + lKey * DQ + lDp;
    const float* bSrc = Qn + (qBase + lQ) * DQ + lQdp;

    for (int kt = 0; kt < 72; kt++) {
        const int keyBase = kt * 128;
        const float* aTile = aSrc + keyBase * DQ;

        ull acc[8][2];
#pragma unroll
        for (int i = 0; i < 8; i++) { acc[i][0] = 0ull; acc[i][1] = 0ull; }

        for (int ch = 0; ch < 18; ch++) {
            __syncthreads();
            {   // key tile slice, value-duplicated
                const float4* s = reinterpret_cast<const float4*>(aTile + ch * 16);
                float4 a0 = s[0], a1 = s[1];
                sm.ld.A[lDp + 0][lKey] = make_float2(a0.x, a0.x);
                sm.ld.A[lDp + 1][lKey] = make_float2(a0.y, a0.y);
                sm.ld.A[lDp + 2][lKey] = make_float2(a0.z, a0.z);
                sm.ld.A[lDp + 3][lKey] = make_float2(a0.w, a0.w);
                sm.ld.A[lDp + 4][lKey] = make_float2(a1.x, a1.x);
                sm.ld.A[lDp + 5][lKey] = make_float2(a1.y, a1.y);
                sm.ld.A[lDp + 6][lKey] = make_float2(a1.z, a1.z);
                sm.ld.A[lDp + 7][lKey] = make_float2(a1.w, a1.w);
            }
            {   // query tile slice
                float4 b = *reinterpret_cast<const float4*>(bSrc + ch * 16);
                sm.ld.B[lQdp + 0][lQ] = b.x;
                sm.ld.B[lQdp + 1][lQ] = b.y;
                sm.ld.B[lQdp + 2][lQ] = b.z;
                sm.ld.B[lQdp + 3][lQ] = b.w;
            }
            __syncthreads();
#pragma unroll
            for (int t = 0; t < 16; t++) {
                ulonglong2 b2  = *reinterpret_cast<const ulonglong2*>(&sm.ld.B[t][q0]);
                ulonglong2 a01 = *reinterpret_cast<const ulonglong2*>(&sm.ld.A[t][k0]);
                ulonglong2 a23 = *reinterpret_cast<const ulonglong2*>(&sm.ld.A[t][k0 + 2]);
                ulonglong2 a45 = *reinterpret_cast<const ulonglong2*>(&sm.ld.A[t][k0 + 4]);
                ulonglong2 a67 = *reinterpret_cast<const ulonglong2*>(&sm.ld.A[t][k0 + 6]);
                acc[0][0] = fma2(a01.x, b2.x, acc[0][0]); acc[0][1] = fma2(a01.x, b2.y, acc[0][1]);
                acc[1][0] = fma2(a01.y, b2.x, acc[1][0]); acc[1][1] = fma2(a01.y, b2.y, acc[1][1]);
                acc[2][0] = fma2(a23.x, b2.x, acc[2][0]); acc[2][1] = fma2(a23.x, b2.y, acc[2][1]);
                acc[3][0] = fma2(a23.y, b2.x, acc[3][0]); acc[3][1] = fma2(a23.y, b2.y, acc[3][1]);
                acc[4][0] = fma2(a45.x, b2.x, acc[4][0]); acc[4][1] = fma2(a45.x, b2.y, acc[4][1]);
                acc[5][0] = fma2(a45.y, b2.x, acc[5][0]); acc[5][1] = fma2(a45.y, b2.y, acc[5][1]);
                acc[6][0] = fma2(a67.x, b2.x, acc[6][0]); acc[6][1] = fma2(a67.x, b2.y, acc[6][1]);
                acc[7][0] = fma2(a67.y, b2.x, acc[7][0]); acc[7][1] = fma2(a67.y, b2.y, acc[7][1]);
            }
        }
        __syncthreads();   // done reading ld-buffers; scores alias them
#pragma unroll
        for (int i = 0; i < 8; i++) {
            *reinterpret_cast<ull*>(&sm.scores[k0 + i][q0])     = acc[i][0];
            *reinterpret_cast<ull*>(&sm.scores[k0 + i][q0 + 2]) = acc[i][1];
        }
        __syncthreads();
        // each thread scans 32 keys of its query's column
        for (int i = 0; i < 32; i++) {
            float v = sm.scores[ksScan + i][qScan];
            if (v > v5[4]) {                       // strict >: ties keep earlier idx
                int gi = keyBase + ksScan + i;
                v5[4] = v; i5[4] = gi;
                if (v5[4] > v5[3]) { float tv = v5[3]; v5[3] = v5[4]; v5[4] = tv; int ti = i5[3]; i5[3] = i5[4]; i5[4] = ti; }
                if (v5[3] > v5[2]) { float tv = v5[2]; v5[2] = v5[3]; v5[3] = tv; int ti = i5[2]; i5[2] = i5[3]; i5[3] = ti; }
                if (v5[2] > v5[1]) { float tv = v5[1]; v5[1] = v5[2]; v5[2] = tv; int ti = i5[1]; i5[1] = i5[2]; i5[2] = ti; }
                if (v5[1] > v5[0]) { float tv = v5[0]; v5[0] = v5[1]; v5[1] = tv; int ti = i5[0]; i5[0] = i5[1]; i5[1] = ti; }
            }
        }
        __syncthreads();   // scores region reused as ld-buffers next tile
    }

    // cross-quarter merge (4 partial top5 lists -> final top5 per query)
    const int ks = tid >> 6;
#pragma unroll
    for (int r = 0; r < 5; r++) {
        sm.cand.v [qScan][ks * 5 + r] = v5[r];
        sm.cand.id[qScan][ks * 5 + r] = i5[r];
    }
    __syncthreads();
    if (tid < 64) {
        int q = tid;
        for (int r = 0; r < 5; r++) {
            float best = -1e30f; int bi = 0x7fffffff; int bj = 0;
            for (int j = 0; j < 20; j++) {
                float v = sm.cand.v[q][j]; int id = sm.cand.id[q][j];
                if (v > best || (v == best && id < bi)) { best = v; bi = id; bj = j; }
            }
            tvals[(qBase + q) * 5 + r] = best;
            tidx [(qBase + q) * 5 + r] = bi;
            sm.cand.v[q][bj] = -1e31f;
        }
    }
}

// ---------------------------------------------------------------------------
// Final assembly:
// y[c,Y,X] = feat + x + (1/36) * sum_{r=1..4} S_r[Y,X] *
//            sum_{dy,dx in [-1,1], (Y+dy,X+dx) in-bounds}
//              x[c, my - dy, mx - dx]   (zero if OOB),  m = top-idx[r] at (Y+dy,X+dx)
// Block: 4 pixels x 64 channels. grid 2304, block 256.
// ---------------------------------------------------------------------------
__global__ void assemble_kernel(const float* __restrict__ x,
                                const float* __restrict__ xT,
                                const float* __restrict__ feat,
                                const float* __restrict__ tvals,
                                const int*   __restrict__ tidx,
                                float* __restrict__ out)
{
    const int tid = threadIdx.x;
    const int pix = blockIdx.x * 4 + (tid >> 6);
    const int c = tid & 63;
    const int Y = pix / Ww, X = pix - Y * Ww;

    float s = 0.f;
#pragma unroll
    for (int r = 1; r < 5; r++) {
        float S = tvals[pix * 5 + r];
        float inner = 0.f;
#pragma unroll
        for (int dy = -1; dy <= 1; dy++) {
            int ly = Y + dy;
            if (ly < 0 || ly >= Hh) continue;
#pragma unroll
            for (int dx = -1; dx <= 1; dx++) {
                int lx = X + dx;
                if (lx < 0 || lx >= Ww) continue;
                int m = tidx[(ly * Ww + lx) * 5 + r];
                int my = m / Ww, mx = m - my * Ww;
                int sy = my - dy, sx = mx - dx;
                if (sy >= 0 && sy < Hh && sx >= 0 && sx < Ww)
                    inner += xT[(sy * Ww + sx) * CIN + c];
            }
        }
        s += S * inner;
    }
    out[c * HW + pix] = feat[c * HW + pix] + x[c * HW + pix] + s * (1.0f / 36.0f);
}

// ---------------------------------------------------------------------------
extern "C" void kernel_launch(void* const* d_in, const int* in_sizes, int n_in,
                              void* d_out, int out_size)
{
    (void)in_sizes; (void)n_in; (void)out_size;
    const float* x  = (const float*)d_in[0];
    const float* W1 = (const float*)d_in[1];
    const float* b1 = (const float*)d_in[2];
    const float* W2 = (const float*)d_in[3];
    const float* b2 = (const float*)d_in[4];
    const float* Wq = (const float*)d_in[5];
    const float* bq = (const float*)d_in[6];
    const float* Wk = (const float*)d_in[7];
    const float* bk = (const float*)d_in[8];
    float* out = (float*)d_out;

    float *t1, *feat, *qb, *kb, *Qn, *Kn, *xT, *tv;
    int* ti;
    cudaGetSymbolAddress((void**)&t1,   g_t1);
    cudaGetSymbolAddress((void**)&feat, g_feat);
    cudaGetSymbolAddress((void**)&qb,   g_q);
    cudaGetSymbolAddress((void**)&kb,   g_k);
    cudaGetSymbolAddress((void**)&Qn,   g_Qn);
    cudaGetSymbolAddress((void**)&Kn,   g_Kn);
    cudaGetSymbolAddress((void**)&xT,   g_xT);
    cudaGetSymbolAddress((void**)&tv,   g_tv);
    cudaGetSymbolAddress((void**)&ti,   g_ti);

    dim3 cblk(32, 8);
    dim3 cgrid64(3, 6, 8);   // Cout=64
    dim3 cgrid32(3, 6, 4);   // Cout=32

    conv3x3_kernel<<<cgrid64, cblk>>>(x,  W1, b1, t1,   1);
    conv3x3_kernel<<<cgrid64, cblk>>>(t1, W2, b2, feat, 1);
    conv3x3_kernel<<<cgrid32, cblk>>>(x,  Wq, bq, qb,   0);
    conv3x3_kernel<<<cgrid32, cblk>>>(x,  Wk, bk, kb,   0);

    patch_norm_kernel<<<LQ, DQ>>>(qb, Qn);
    patch_norm_kernel<<<LQ, DQ>>>(kb, Kn);
    transpose_x_kernel<<<(CIN * HW + 255) / 256, 256>>>(x, xT);

    sim_top5_kernel<<<144, 256>>>(Kn, Qn, tv, ti);

    assemble_kernel<<<HW / 4, 256>>>(x, xT, feat, tv, ti, out);
}

// round 7
// speedup vs baseline: 1.1889x; 1.1889x over previous
#include <cuda_runtime.h>
#include <cuda_bf16.h>

// ---------------------------------------------------------------------------
// TransformerV2: conv feature branch + patch-similarity top-5 attention.
// Shapes fixed by the problem: B=1, Cin=64, Cq=32, H=W=96, L=9216, D=32*9=288.
// R6: software-pipelined sim kernel (reg prefetch + double-buffered smem,
//     1 barrier/chunk) and pipelined full-grid convs.
// ---------------------------------------------------------------------------

#define Hh 96
#define Ww 96
#define HW 9216         // 96*96
#define CIN 64
#define CQ  32
#define DQ  288         // CQ*9
#define LQ  9216

typedef unsigned long long ull;

// -------------------------- scratch (static, no allocs) --------------------
__device__ float g_t1  [CIN * HW];     // relu(conv1(x))
__device__ float g_feat[CIN * HW];     // relu(conv2(t1))
__device__ float g_q   [CQ  * HW];
__device__ float g_k   [CQ  * HW];
__device__ float g_Qn  [LQ * DQ];      // normalized query patch vectors [L][288]
__device__ float g_Kn  [LQ * DQ];      // normalized key   patch vectors [L][288]
__device__ float g_xT  [HW * CIN];     // x transposed to [pixel][channel]
__device__ float g_tv  [LQ * 5];       // top5 values  [L][5]
__device__ int   g_ti  [LQ * 5];       // top5 indices [L][5]

// ---------------------------------------------------------------------------
// 3x3 SAME conv, Cin=64 fixed, Cout multiple of 8; software pipelined.
// RPT = rows-per-thread. Tile 32(w) x (8*RPT)(h), 8 output chans per block.
// grid (3, 96/(8*RPT), Cout/8), block (32, 8).
// ---------------------------------------------------------------------------
template<int RPT>
__global__ void __launch_bounds__(256) conv3x3_t(
    const float* __restrict__ in,   // [64][96][96]
    const float* __restrict__ wgt,  // [Cout][64][3][3]
    const float* __restrict__ bias, // [Cout]
    float* __restrict__ out,        // [Cout][96][96]
    int doRelu)
{
    constexpr int TH = 8 * RPT;
    constexpr int TL = (TH + 2) * 34;          // floats per input tile
    constexpr int NP = (TL + 255) / 256;       // prefetch regs per thread

    __shared__ float tin[2][TH + 2][36];
    __shared__ float wsm[64][72];              // [cin][o*9+k]

    const int tx = threadIdx.x;                // 0..31
    const int ty = threadIdx.y;                // 0..7
    const int tid = ty * 32 + tx;
    const int x0 = blockIdx.x * 32;
    const int y0 = blockIdx.y * TH;
    const int og = blockIdx.z * 8;

    for (int i = tid; i < 8 * 64 * 9; i += 256) {
        int o = i / 576, rem = i - o * 576, ci = rem / 9, k = rem - ci * 9;
        wsm[ci][o * 9 + k] = wgt[((og + o) * 64 + ci) * 9 + k];
    }

    float pf[NP];
#pragma unroll
    for (int j = 0; j < NP; j++) {             // prefetch ci = 0
        int i = tid + j * 256;
        float v = 0.f;
        if (i < TL) {
            int r = i / 34, c = i - r * 34;
            int gy = y0 - 1 + r, gx = x0 - 1 + c;
            if (gy >= 0 && gy < Hh && gx >= 0 && gx < Ww)
                v = in[gy * Ww + gx];          // ci=0 plane
        }
        pf[j] = v;
    }

    float acc[8][RPT];
#pragma unroll
    for (int o = 0; o < 8; o++)
#pragma unroll
        for (int rr = 0; rr < RPT; rr++) acc[o][rr] = 0.f;

    for (int ci = 0; ci < 64; ci++) {
        const int buf = ci & 1;
#pragma unroll
        for (int j = 0; j < NP; j++) {
            int i = tid + j * 256;
            if (i < TL) {
                int r = i / 34, c = i - r * 34;
                tin[buf][r][c] = pf[j];
            }
        }
        __syncthreads();

        if (ci < 63) {                          // prefetch next plane
            const float* p = in + (ci + 1) * HW;
#pragma unroll
            for (int j = 0; j < NP; j++) {
                int i = tid + j * 256;
                float v = 0.f;
                if (i < TL) {
                    int r = i / 34, c = i - r * 34;
                    int gy = y0 - 1 + r, gx = x0 - 1 + c;
                    if (gy >= 0 && gy < Hh && gx >= 0 && gx < Ww)
                        v = p[gy * Ww + gx];
                }
                pf[j] = v;
            }
        }

        float v[RPT][9];
#pragma unroll
        for (int rr = 0; rr < RPT; rr++) {
            int yl = ty + 8 * rr;
#pragma unroll
            for (int dy = 0; dy < 3; dy++)
#pragma unroll
                for (int dx = 0; dx < 3; dx++)
                    v[rr][dy * 3 + dx] = tin[buf][yl + dy][tx + dx];
        }
#pragma unroll
        for (int o = 0; o < 8; o++) {
            float w9[9];
#pragma unroll
            for (int k = 0; k < 9; k++) w9[k] = wsm[ci][o * 9 + k];
#pragma unroll
            for (int rr = 0; rr < RPT; rr++)
#pragma unroll
                for (int k = 0; k < 9; k++)
                    acc[o][rr] = fmaf(v[rr][k], w9[k], acc[o][rr]);
        }
    }

    const int gx = x0 + tx;
#pragma unroll
    for (int o = 0; o < 8; o++) {
        float b = bias[og + o];
#pragma unroll
        for (int rr = 0; rr < RPT; rr++) {
            int gy = y0 + ty + 8 * rr;
            float r = acc[o][rr] + b;
            if (doRelu) r = fmaxf(r, 0.f);
            out[(og + o) * HW + gy * Ww + gx] = r;
        }
    }
}

// ---------------------------------------------------------------------------
// Build L2-normalized 3x3 patch vectors: one block per spatial position,
// 288 threads (one per patch element). grid 9216, block 288.
// ---------------------------------------------------------------------------
__global__ void patch_norm_kernel(const float* __restrict__ f,  // [32][96][96]
                                  float* __restrict__ vec)       // [L][288]
{
    const int l = blockIdx.x;
    const int y = l / Ww, x = l - y * Ww;
    const int d = threadIdx.x;          // 0..287
    const int c = d / 9, ij = d - c * 9;
    const int dy = ij / 3 - 1, dx = ij % 3 - 1;
    const int yy = y + dy, xx = x + dx;

    float v = 0.f;
    if (yy >= 0 && yy < Hh && xx >= 0 && xx < Ww)
        v = f[c * HW + yy * Ww + xx];

    __shared__ float red[9];
    __shared__ float nrm;
    float s = v * v;
#pragma unroll
    for (int off = 16; off > 0; off >>= 1)
        s += __shfl_down_sync(0xffffffffu, s, off);
    if ((d & 31) == 0) red[d >> 5] = s;
    __syncthreads();
    if (d == 0) {
        float t = 0.f;
#pragma unroll
        for (int i = 0; i < 9; i++) t += red[i];
        float n = sqrtf(t);
        nrm = fmaxf(n, 1e-12f);
    }
    __syncthreads();
    vec[l * DQ + d] = v / nrm;
}

// ---------------------------------------------------------------------------
// x -> xT  (CHW -> HWC) for coalesced channel gathers in assembly.
// ---------------------------------------------------------------------------
__global__ void transpose_x_kernel(const float* __restrict__ x,
                                   float* __restrict__ xT)
{
    int i = blockIdx.x * 256 + threadIdx.x;
    if (i < CIN * HW) {
        int p = i >> 6, c = i & 63;
        xT[i] = x[c * HW + p];
    }
}

// ---------------------------------------------------------------------------
// Fused similarity GEMM + streaming top-5 (software pipelined).
// Per CTA: 64 queries; stream 72 key tiles of 128; 256 threads.
// Per depth chunk (16): prefetch next chunk (regs) right after the single
// barrier; compute overlaps the LDG. Key tile stored value-duplicated so
// FFMA2 a-frags load pre-packed.
// grid 144, block 256.
// ---------------------------------------------------------------------------
__device__ __forceinline__ ull fma2(ull a, ull b, ull c) {
    ull d;
    asm("fma.rn.f32x2 %0, %1, %2, %3;" : "=l"(d) : "l"(a), "l"(b), "l"(c));
    return d;
}

__global__ void __launch_bounds__(256, 1) sim_top5_kernel(
    const float* __restrict__ Kn,   // [L][288]
    const float* __restrict__ Qn,   // [L][288]
    float* __restrict__ tvals,      // [L][5]
    int*   __restrict__ tidx)       // [L][5]
{
    __shared__ __align__(16) union SMem {
        struct { float2 A[2][16][128]; float B[2][16][64]; } ld;  // 32K + 8K
        float scores[128][66];                                    // 33792 B
        struct { float v[64][20]; int id[64][20]; } cand;         // 10240 B
    } sm;

    const int tid = threadIdx.x;
    const int txq = tid & 15;            // query group
    const int tyk = tid >> 4;            // key group
    const int k0 = tyk * 8;
    const int q0 = txq * 4;
    const int qBase = blockIdx.x * 64;

    const int lKey = tid >> 1, lDp = (tid & 1) * 8;      // A-tile loaders
    const int lQ   = tid >> 2, lQdp = (tid & 3) * 4;     // B-tile loaders
    const int qScan = tid & 63, ksScan = (tid >> 6) * 32;

    float v5[5]; int i5[5];
#pragma unroll
    for (int r = 0; r < 5; r++) { v5[r] = -1e30f; i5[r] = 0; }

    const float* aBase = Kn + lKey * DQ + lDp;            // +kt*128*288 + ch*16
    const float* bBase = Qn + (qBase + lQ) * DQ + lQdp;   // +ch*16

    // prefetch (kt=0, ch=0)
    float4 pa0 = *reinterpret_cast<const float4*>(aBase);
    float4 pa1 = *reinterpret_cast<const float4*>(aBase + 4);
    float4 pb  = *reinterpret_cast<const float4*>(bBase);

    for (int kt = 0; kt < 72; kt++) {
        const int keyBase = kt * 128;

        ull acc[8][2];
#pragma unroll
        for (int i = 0; i < 8; i++) { acc[i][0] = 0ull; acc[i][1] = 0ull; }

        for (int ch = 0; ch < 18; ch++) {
            const int buf = ch & 1;
            // stage prefetched regs (A value-duplicated, B plain)
            sm.ld.A[buf][lDp + 0][lKey] = make_float2(pa0.x, pa0.x);
            sm.ld.A[buf][lDp + 1][lKey] = make_float2(pa0.y, pa0.y);
            sm.ld.A[buf][lDp + 2][lKey] = make_float2(pa0.z, pa0.z);
            sm.ld.A[buf][lDp + 3][lKey] = make_float2(pa0.w, pa0.w);
            sm.ld.A[buf][lDp + 4][lKey] = make_float2(pa1.x, pa1.x);
            sm.ld.A[buf][lDp + 5][lKey] = make_float2(pa1.y, pa1.y);
            sm.ld.A[buf][lDp + 6][lKey] = make_float2(pa1.z, pa1.z);
            sm.ld.A[buf][lDp + 7][lKey] = make_float2(pa1.w, pa1.w);
            sm.ld.B[buf][lQdp + 0][lQ] = pb.x;
            sm.ld.B[buf][lQdp + 1][lQ] = pb.y;
            sm.ld.B[buf][lQdp + 2][lQ] = pb.z;
            sm.ld.B[buf][lQdp + 3][lQ] = pb.w;
            __syncthreads();

            // prefetch next chunk (overlaps with compute below)
            {
                int nch = ch + 1, nkt = kt;
                if (nch == 18) { nch = 0; nkt = kt + 1; }
                if (nkt < 72) {
                    const float* ap = aBase + nkt * (128 * DQ) + nch * 16;
                    pa0 = *reinterpret_cast<const float4*>(ap);
                    pa1 = *reinterpret_cast<const float4*>(ap + 4);
                    pb  = *reinterpret_cast<const float4*>(bBase + nch * 16);
                }
            }

#pragma unroll
            for (int t = 0; t < 16; t++) {
                ulonglong2 b2  = *reinterpret_cast<const ulonglong2*>(&sm.ld.B[buf][t][q0]);
                ulonglong2 a01 = *reinterpret_cast<const ulonglong2*>(&sm.ld.A[buf][t][k0]);
                ulonglong2 a23 = *reinterpret_cast<const ulonglong2*>(&sm.ld.A[buf][t][k0 + 2]);
                ulonglong2 a45 = *reinterpret_cast<const ulonglong2*>(&sm.ld.A[buf][t][k0 + 4]);
                ulonglong2 a67 = *reinterpret_cast<const ulonglong2*>(&sm.ld.A[buf][t][k0 + 6]);
                acc[0][0] = fma2(a01.x, b2.x, acc[0][0]); acc[0][1] = fma2(a01.x, b2.y, acc[0][1]);
                acc[1][0] = fma2(a01.y, b2.x, acc[1][0]); acc[1][1] = fma2(a01.y, b2.y, acc[1][1]);
                acc[2][0] = fma2(a23.x, b2.x, acc[2][0]); acc[2][1] = fma2(a23.x, b2.y, acc[2][1]);
                acc[3][0] = fma2(a23.y, b2.x, acc[3][0]); acc[3][1] = fma2(a23.y, b2.y, acc[3][1]);
                acc[4][0] = fma2(a45.x, b2.x, acc[4][0]); acc[4][1] = fma2(a45.x, b2.y, acc[4][1]);
                acc[5][0] = fma2(a45.y, b2.x, acc[5][0]); acc[5][1] = fma2(a45.y, b2.y, acc[5][1]);
                acc[6][0] = fma2(a67.x, b2.x, acc[6][0]); acc[6][1] = fma2(a67.x, b2.y, acc[6][1]);
                acc[7][0] = fma2(a67.y, b2.x, acc[7][0]); acc[7][1] = fma2(a67.y, b2.y, acc[7][1]);
            }
        }
        __syncthreads();   // all compute done reading ld buffers; scores alias them
#pragma unroll
        for (int i = 0; i < 8; i++) {
            *reinterpret_cast<ull*>(&sm.scores[k0 + i][q0])     = acc[i][0];
            *reinterpret_cast<ull*>(&sm.scores[k0 + i][q0 + 2]) = acc[i][1];
        }
        __syncthreads();
        // each thread scans 32 keys of its query's column
        for (int i = 0; i < 32; i++) {
            float v = sm.scores[ksScan + i][qScan];
            if (v > v5[4]) {                       // strict >: ties keep earlier idx
                int gi = keyBase + ksScan + i;
                v5[4] = v; i5[4] = gi;
                if (v5[4] > v5[3]) { float tv = v5[3]; v5[3] = v5[4]; v5[4] = tv; int ti = i5[3]; i5[3] = i5[4]; i5[4] = ti; }
                if (v5[3] > v5[2]) { float tv = v5[2]; v5[2] = v5[3]; v5[3] = tv; int ti = i5[2]; i5[2] = i5[3]; i5[3] = ti; }
                if (v5[2] > v5[1]) { float tv = v5[1]; v5[1] = v5[2]; v5[2] = tv; int ti = i5[1]; i5[1] = i5[2]; i5[2] = ti; }
                if (v5[1] > v5[0]) { float tv = v5[0]; v5[0] = v5[1]; v5[1] = tv; int ti = i5[0]; i5[0] = i5[1]; i5[1] = ti; }
            }
        }
        __syncthreads();   // scores region reused as ld-buffers next tile
    }

    // cross-quarter merge (4 partial top5 lists -> final top5 per query)
    const int ks = tid >> 6;
#pragma unroll
    for (int r = 0; r < 5; r++) {
        sm.cand.v [qScan][ks * 5 + r] = v5[r];
        sm.cand.id[qScan][ks * 5 + r] = i5[r];
    }
    __syncthreads();
    if (tid < 64) {
        int q = tid;
        for (int r = 0; r < 5; r++) {
            float best = -1e30f; int bi = 0x7fffffff; int bj = 0;
            for (int j = 0; j < 20; j++) {
                float v = sm.cand.v[q][j]; int id = sm.cand.id[q][j];
                if (v > best || (v == best && id < bi)) { best = v; bi = id; bj = j; }
            }
            tvals[(qBase + q) * 5 + r] = best;
            tidx [(qBase + q) * 5 + r] = bi;
            sm.cand.v[q][bj] = -1e31f;
        }
    }
}

// ---------------------------------------------------------------------------
// Final assembly:
// y[c,Y,X] = feat + x + (1/36) * sum_{r=1..4} S_r[Y,X] *
//            sum_{dy,dx in [-1,1], (Y+dy,X+dx) in-bounds}
//              x[c, my - dy, mx - dx]   (zero if OOB),  m = top-idx[r] at (Y+dy,X+dx)
// Block: 4 pixels x 64 channels. grid 2304, block 256.
// ---------------------------------------------------------------------------
__global__ void assemble_kernel(const float* __restrict__ x,
                                const float* __restrict__ xT,
                                const float* __restrict__ feat,
                                const float* __restrict__ tvals,
                                const int*   __restrict__ tidx,
                                float* __restrict__ out)
{
    const int tid = threadIdx.x;
    const int pix = blockIdx.x * 4 + (tid >> 6);
    const int c = tid & 63;
    const int Y = pix / Ww, X = pix - Y * Ww;

    float s = 0.f;
#pragma unroll
    for (int r = 1; r < 5; r++) {
        float S = tvals[pix * 5 + r];
        float inner = 0.f;
#pragma unroll
        for (int dy = -1; dy <= 1; dy++) {
            int ly = Y + dy;
            if (ly < 0 || ly >= Hh) continue;
#pragma unroll
            for (int dx = -1; dx <= 1; dx++) {
                int lx = X + dx;
                if (lx < 0 || lx >= Ww) continue;
                int m = tidx[(ly * Ww + lx) * 5 + r];
                int my = m / Ww, mx = m - my * Ww;
                int sy = my - dy, sx = mx - dx;
                if (sy >= 0 && sy < Hh && sx >= 0 && sx < Ww)
                    inner += xT[(sy * Ww + sx) * CIN + c];
            }
        }
        s += S * inner;
    }
    out[c * HW + pix] = feat[c * HW + pix] + x[c * HW + pix] + s * (1.0f / 36.0f);
}

// ---------------------------------------------------------------------------
extern "C" void kernel_launch(void* const* d_in, const int* in_sizes, int n_in,
                              void* d_out, int out_size)
{
    (void)in_sizes; (void)n_in; (void)out_size;
    const float* x  = (const float*)d_in[0];
    const float* W1 = (const float*)d_in[1];
    const float* b1 = (const float*)d_in[2];
    const float* W2 = (const float*)d_in[3];
    const float* b2 = (const float*)d_in[4];
    const float* Wq = (const float*)d_in[5];
    const float* bq = (const float*)d_in[6];
    const float* Wk = (const float*)d_in[7];
    const float* bk = (const float*)d_in[8];
    float* out = (float*)d_out;

    float *t1, *feat, *qb, *kb, *Qn, *Kn, *xT, *tv;
    int* ti;
    cudaGetSymbolAddress((void**)&t1,   g_t1);
    cudaGetSymbolAddress((void**)&feat, g_feat);
    cudaGetSymbolAddress((void**)&qb,   g_q);
    cudaGetSymbolAddress((void**)&kb,   g_k);
    cudaGetSymbolAddress((void**)&Qn,   g_Qn);
    cudaGetSymbolAddress((void**)&Kn,   g_Kn);
    cudaGetSymbolAddress((void**)&xT,   g_xT);
    cudaGetSymbolAddress((void**)&tv,   g_tv);
    cudaGetSymbolAddress((void**)&ti,   g_ti);

    dim3 cblk(32, 8);

    // 64-ch convs: RPT=2, tile 32x16, grid 144. 32-ch convs: RPT=1, tile 32x8, grid 144.
    conv3x3_t<2><<<dim3(3, 6, 8),  cblk>>>(x,  W1, b1, t1,   1);
    conv3x3_t<2><<<dim3(3, 6, 8),  cblk>>>(t1, W2, b2, feat, 1);
    conv3x3_t<1><<<dim3(3, 12, 4), cblk>>>(x,  Wq, bq, qb,   0);
    conv3x3_t<1><<<dim3(3, 12, 4), cblk>>>(x,  Wk, bk, kb,   0);

    patch_norm_kernel<<<LQ, DQ>>>(qb, Qn);
    patch_norm_kernel<<<LQ, DQ>>>(kb, Kn);
    transpose_x_kernel<<<(CIN * HW + 255) / 256, 256>>>(x, xT);

    sim_top5_kernel<<<144, 256>>>(Kn, Qn, tv, ti);

    assemble_kernel<<<HW / 4, 256>>>(x, xT, feat, tv, ti, out);
}

// round 9
// speedup vs baseline: 1.3423x; 1.1290x over previous
#include <cuda_runtime.h>
#include <cuda_bf16.h>

// ---------------------------------------------------------------------------
// TransformerV2: conv feature branch + patch-similarity top-5 attention.
// Shapes fixed: B=1, Cin=64, Cq=32, H=W=96, L=9216, D=32*9=288.
// R7: sim restructured to be FMA-bound: warp-per-query-group (uniform B
//     broadcast LDS), 8x8 thread tile, A plain in smem + register packing,
//     256-key tiles, conflict-free score buffer. Convs at 2 CTAs/SM.
// ---------------------------------------------------------------------------

#define Hh 96
#define Ww 96
#define HW 9216
#define CIN 64
#define CQ  32
#define DQ  288
#define LQ  9216

typedef unsigned long long ull;

// -------------------------- scratch (static, no allocs) --------------------
__device__ float g_t1  [CIN * HW];
__device__ float g_feat[CIN * HW];
__device__ float g_q   [CQ  * HW];
__device__ float g_k   [CQ  * HW];
__device__ float g_Qn  [LQ * DQ];
__device__ float g_Kn  [LQ * DQ];
__device__ float g_xT  [HW * CIN];
__device__ float g_tv  [LQ * 5];
__device__ int   g_ti  [LQ * 5];

// ---------------------------------------------------------------------------
// 3x3 SAME conv, Cin=64, 4 output channels per block (2 CTAs/SM), pipelined.
// grid (3, 96/(8*RPT), Cout/4), block (32, 8).
// ---------------------------------------------------------------------------
template<int RPT>
__global__ void __launch_bounds__(256) conv3x3_t(
    const float* __restrict__ in,
    const float* __restrict__ wgt,
    const float* __restrict__ bias,
    float* __restrict__ out,
    int doRelu)
{
    constexpr int TH = 8 * RPT;
    constexpr int TL = (TH + 2) * 34;
    constexpr int NP = (TL + 255) / 256;

    __shared__ float tin[2][TH + 2][36];
    __shared__ float wsm[64][36];              // [cin][o*9+k], 4 outs

    const int tx = threadIdx.x;
    const int ty = threadIdx.y;
    const int tid = ty * 32 + tx;
    const int x0 = blockIdx.x * 32;
    const int y0 = blockIdx.y * TH;
    const int og = blockIdx.z * 4;

    for (int i = tid; i < 4 * 64 * 9; i += 256) {
        int o = i / 576, rem = i - o * 576, ci = rem / 9, k = rem - ci * 9;
        wsm[ci][o * 9 + k] = wgt[((og + o) * 64 + ci) * 9 + k];
    }

    float pf[NP];
#pragma unroll
    for (int j = 0; j < NP; j++) {
        int i = tid + j * 256;
        float v = 0.f;
        if (i < TL) {
            int r = i / 34, c = i - r * 34;
            int gy = y0 - 1 + r, gx = x0 - 1 + c;
            if (gy >= 0 && gy < Hh && gx >= 0 && gx < Ww)
                v = in[gy * Ww + gx];
        }
        pf[j] = v;
    }

    float acc[4][RPT];
#pragma unroll
    for (int o = 0; o < 4; o++)
#pragma unroll
        for (int rr = 0; rr < RPT; rr++) acc[o][rr] = 0.f;

    for (int ci = 0; ci < 64; ci++) {
        const int buf = ci & 1;
#pragma unroll
        for (int j = 0; j < NP; j++) {
            int i = tid + j * 256;
            if (i < TL) {
                int r = i / 34, c = i - r * 34;
                tin[buf][r][c] = pf[j];
            }
        }
        __syncthreads();

        if (ci < 63) {
            const float* p = in + (ci + 1) * HW;
#pragma unroll
            for (int j = 0; j < NP; j++) {
                int i = tid + j * 256;
                float v = 0.f;
                if (i < TL) {
                    int r = i / 34, c = i - r * 34;
                    int gy = y0 - 1 + r, gx = x0 - 1 + c;
                    if (gy >= 0 && gy < Hh && gx >= 0 && gx < Ww)
                        v = p[gy * Ww + gx];
                }
                pf[j] = v;
            }
        }

        float v[RPT][9];
#pragma unroll
        for (int rr = 0; rr < RPT; rr++) {
            int yl = ty + 8 * rr;
#pragma unroll
            for (int dy = 0; dy < 3; dy++)
#pragma unroll
                for (int dx = 0; dx < 3; dx++)
                    v[rr][dy * 3 + dx] = tin[buf][yl + dy][tx + dx];
        }
#pragma unroll
        for (int o = 0; o < 4; o++) {
            float w9[9];
#pragma unroll
            for (int k = 0; k < 9; k++) w9[k] = wsm[ci][o * 9 + k];
#pragma unroll
            for (int rr = 0; rr < RPT; rr++)
#pragma unroll
                for (int k = 0; k < 9; k++)
                    acc[o][rr] = fmaf(v[rr][k], w9[k], acc[o][rr]);
        }
    }

    const int gx = x0 + tx;
#pragma unroll
    for (int o = 0; o < 4; o++) {
        float b = bias[og + o];
#pragma unroll
        for (int rr = 0; rr < RPT; rr++) {
            int gy = y0 + ty + 8 * rr;
            float r = acc[o][rr] + b;
            if (doRelu) r = fmaxf(r, 0.f);
            out[(og + o) * HW + gy * Ww + gx] = r;
        }
    }
}

// ---------------------------------------------------------------------------
__global__ void patch_norm_kernel(const float* __restrict__ f,
                                  float* __restrict__ vec)
{
    const int l = blockIdx.x;
    const int y = l / Ww, x = l - y * Ww;
    const int d = threadIdx.x;
    const int c = d / 9, ij = d - c * 9;
    const int dy = ij / 3 - 1, dx = ij % 3 - 1;
    const int yy = y + dy, xx = x + dx;

    float v = 0.f;
    if (yy >= 0 && yy < Hh && xx >= 0 && xx < Ww)
        v = f[c * HW + yy * Ww + xx];

    __shared__ float red[9];
    __shared__ float nrm;
    float s = v * v;
#pragma unroll
    for (int off = 16; off > 0; off >>= 1)
        s += __shfl_down_sync(0xffffffffu, s, off);
    if ((d & 31) == 0) red[d >> 5] = s;
    __syncthreads();
    if (d == 0) {
        float t = 0.f;
#pragma unroll
        for (int i = 0; i < 9; i++) t += red[i];
        nrm = fmaxf(sqrtf(t), 1e-12f);
    }
    __syncthreads();
    vec[l * DQ + d] = v / nrm;
}

// ---------------------------------------------------------------------------
__global__ void transpose_x_kernel(const float* __restrict__ x,
                                   float* __restrict__ xT)
{
    int i = blockIdx.x * 256 + threadIdx.x;
    if (i < CIN * HW) {
        int p = i >> 6, c = i & 63;
        xT[i] = x[c * HW + p];
    }
}

// ---------------------------------------------------------------------------
// Fused similarity GEMM + streaming top-5.
// CTA: 64 queries, 36 key tiles of 256, 256 threads (8 warps).
// Warp w owns queries [w*8, w*8+8); lane l owns keys [l*8, l*8+8) of the tile.
// Thread tile 8x8; FFMA2 with query-pairs packed (contiguous in smem) and
// key scalars duplicated via register mov.b64. B LDS are uniform-address
// (warp broadcast); A LDS are full-width distinct.
// grid 144, block 256.
// ---------------------------------------------------------------------------
__device__ __forceinline__ ull fma2(ull a, ull b, ull c) {
    ull d;
    asm("fma.rn.f32x2 %0, %1, %2, %3;" : "=l"(d) : "l"(a), "l"(b), "l"(c));
    return d;
}
__device__ __forceinline__ ull packdup(float v) {
    ull d;
    asm("mov.b64 %0, {%1, %1};" : "=l"(d) : "f"(v));
    return d;
}

__global__ void __launch_bounds__(256, 1) sim_top5_kernel(
    const float* __restrict__ Kn,   // [L][288]
    const float* __restrict__ Qn,   // [L][288]
    float* __restrict__ tvals,      // [L][5]
    int*   __restrict__ tidx)       // [L][5]
{
    __shared__ __align__(16) union SMem {
        struct { float A[2][16][256]; float B[2][16][64]; } ld;  // 32K + 8K
        float scores[128][67];                                   // 34304 B
        struct { float v[64][20]; int id[64][20]; } cand;        // 10240 B
    } sm;

    const int tid  = threadIdx.x;
    const int lane = tid & 31;
    const int warp = tid >> 5;
    const int qBase = blockIdx.x * 64;

    // staging roles
    const int sq  = tid >> 2;           // B: query 0..63
    const int sdq = (tid & 3) * 4;      // B: depth sub-offset
    // scan roles
    const int qScan = tid & 63;
    const int sSpan = (tid >> 6) * 32;

    float v5[5]; int i5[5];
#pragma unroll
    for (int r = 0; r < 5; r++) { v5[r] = -1e30f; i5[r] = 0; }

    const float* aSrc = Kn + tid * DQ;                  // + kt*256*DQ + ch*16
    const float* bSrc = Qn + (qBase + sq) * DQ + sdq;   // + ch*16

    // prefetch (kt=0, ch=0)
    float4 pa0 = *reinterpret_cast<const float4*>(aSrc);
    float4 pa1 = *reinterpret_cast<const float4*>(aSrc + 4);
    float4 pa2 = *reinterpret_cast<const float4*>(aSrc + 8);
    float4 pa3 = *reinterpret_cast<const float4*>(aSrc + 12);
    float4 pb  = *reinterpret_cast<const float4*>(bSrc);

    for (int kt = 0; kt < 36; kt++) {
        ull acc[8][4];
#pragma unroll
        for (int kk = 0; kk < 8; kk++)
#pragma unroll
            for (int qp = 0; qp < 4; qp++) acc[kk][qp] = 0ull;

        for (int ch = 0; ch < 18; ch++) {
            const int buf = ch & 1;
            // stage A: thread = one key row, 16 depth values
            sm.ld.A[buf][ 0][tid] = pa0.x; sm.ld.A[buf][ 1][tid] = pa0.y;
            sm.ld.A[buf][ 2][tid] = pa0.z; sm.ld.A[buf][ 3][tid] = pa0.w;
            sm.ld.A[buf][ 4][tid] = pa1.x; sm.ld.A[buf][ 5][tid] = pa1.y;
            sm.ld.A[buf][ 6][tid] = pa1.z; sm.ld.A[buf][ 7][tid] = pa1.w;
            sm.ld.A[buf][ 8][tid] = pa2.x; sm.ld.A[buf][ 9][tid] = pa2.y;
            sm.ld.A[buf][10][tid] = pa2.z; sm.ld.A[buf][11][tid] = pa2.w;
            sm.ld.A[buf][12][tid] = pa3.x; sm.ld.A[buf][13][tid] = pa3.y;
            sm.ld.A[buf][14][tid] = pa3.z; sm.ld.A[buf][15][tid] = pa3.w;
            // stage B
            sm.ld.B[buf][sdq + 0][sq] = pb.x;
            sm.ld.B[buf][sdq + 1][sq] = pb.y;
            sm.ld.B[buf][sdq + 2][sq] = pb.z;
            sm.ld.B[buf][sdq + 3][sq] = pb.w;
            __syncthreads();

            // prefetch next chunk (overlaps compute)
            {
                int nch = ch + 1, nkt = kt;
                if (nch == 18) { nch = 0; nkt = kt + 1; }
                if (nkt < 36) {
                    const float* ap = aSrc + nkt * (256 * DQ) + nch * 16;
                    pa0 = *reinterpret_cast<const float4*>(ap);
                    pa1 = *reinterpret_cast<const float4*>(ap + 4);
                    pa2 = *reinterpret_cast<const float4*>(ap + 8);
                    pa3 = *reinterpret_cast<const float4*>(ap + 12);
                    pb  = *reinterpret_cast<const float4*>(bSrc + nch * 16);
                }
            }

#pragma unroll
            for (int t = 0; t < 16; t++) {
                float4 a0 = *reinterpret_cast<const float4*>(&sm.ld.A[buf][t][lane * 8]);
                float4 a1 = *reinterpret_cast<const float4*>(&sm.ld.A[buf][t][lane * 8 + 4]);
                ulonglong2 bb0 = *reinterpret_cast<const ulonglong2*>(&sm.ld.B[buf][t][warp * 8]);
                ulonglong2 bb1 = *reinterpret_cast<const ulonglong2*>(&sm.ld.B[buf][t][warp * 8 + 4]);
                const ull b0 = bb0.x, b1 = bb0.y, b2 = bb1.x, b3 = bb1.y;
                ull ad;
#define SIM_ROW(KK, VAL)                                    \
                ad = packdup(VAL);                          \
                acc[KK][0] = fma2(ad, b0, acc[KK][0]);      \
                acc[KK][1] = fma2(ad, b1, acc[KK][1]);      \
                acc[KK][2] = fma2(ad, b2, acc[KK][2]);      \
                acc[KK][3] = fma2(ad, b3, acc[KK][3]);
                SIM_ROW(0, a0.x) SIM_ROW(1, a0.y) SIM_ROW(2, a0.z) SIM_ROW(3, a0.w)
                SIM_ROW(4, a1.x) SIM_ROW(5, a1.y) SIM_ROW(6, a1.z) SIM_ROW(7, a1.w)
#undef SIM_ROW
            }
        }

        // ------- scores + scan, two 128-key half passes -------
#pragma unroll
        for (int h = 0; h < 2; h++) {
            __syncthreads();     // prior reads of ld/scores done
            if ((lane >> 4) == h) {
                const int r0 = lane * 8 - h * 128;
#pragma unroll
                for (int kk = 0; kk < 8; kk++)
#pragma unroll
                    for (int qp = 0; qp < 4; qp++) {
                        float2 f = *reinterpret_cast<float2*>(&acc[kk][qp]);
                        sm.scores[r0 + kk][warp * 8 + qp * 2]     = f.x;
                        sm.scores[r0 + kk][warp * 8 + qp * 2 + 1] = f.y;
                    }
            }
            __syncthreads();
            const int gBase = kt * 256 + h * 128 + sSpan;
            for (int i = 0; i < 32; i++) {
                float v = sm.scores[sSpan + i][qScan];
                if (v > v5[4]) {
                    int gi = gBase + i;
                    v5[4] = v; i5[4] = gi;
                    if (v5[4] > v5[3]) { float tv = v5[3]; v5[3] = v5[4]; v5[4] = tv; int ti = i5[3]; i5[3] = i5[4]; i5[4] = ti; }
                    if (v5[3] > v5[2]) { float tv = v5[2]; v5[2] = v5[3]; v5[3] = tv; int ti = i5[2]; i5[2] = i5[3]; i5[3] = ti; }
                    if (v5[2] > v5[1]) { float tv = v5[1]; v5[1] = v5[2]; v5[2] = tv; int ti = i5[1]; i5[1] = i5[2]; i5[2] = ti; }
                    if (v5[1] > v5[0]) { float tv = v5[0]; v5[0] = v5[1]; v5[1] = tv; int ti = i5[0]; i5[0] = i5[1]; i5[1] = ti; }
                }
            }
        }
        __syncthreads();   // scan done before ld-buffers are re-staged
    }

    // cross-group merge (4 partial top5 lists per query)
    const int grp = tid >> 6;
#pragma unroll
    for (int r = 0; r < 5; r++) {
        sm.cand.v [qScan][grp * 5 + r] = v5[r];
        sm.cand.id[qScan][grp * 5 + r] = i5[r];
    }
    __syncthreads();
    if (tid < 64) {
        int q = tid;
        for (int r = 0; r < 5; r++) {
            float best = -1e30f; int bi = 0x7fffffff; int bj = 0;
            for (int j = 0; j < 20; j++) {
                float v = sm.cand.v[q][j]; int id = sm.cand.id[q][j];
                if (v > best || (v == best && id < bi)) { best = v; bi = id; bj = j; }
            }
            tvals[(qBase + q) * 5 + r] = best;
            tidx [(qBase + q) * 5 + r] = bi;
            sm.cand.v[q][bj] = -1e31f;
        }
    }
}

// ---------------------------------------------------------------------------
__global__ void assemble_kernel(const float* __restrict__ x,
                                const float* __restrict__ xT,
                                const float* __restrict__ feat,
                                const float* __restrict__ tvals,
                                const int*   __restrict__ tidx,
                                float* __restrict__ out)
{
    const int tid = threadIdx.x;
    const int pix = blockIdx.x * 4 + (tid >> 6);
    const int c = tid & 63;
    const int Y = pix / Ww, X = pix - Y * Ww;

    float s = 0.f;
#pragma unroll
    for (int r = 1; r < 5; r++) {
        float S = tvals[pix * 5 + r];
        float inner = 0.f;
#pragma unroll
        for (int dy = -1; dy <= 1; dy++) {
            int ly = Y + dy;
            if (ly < 0 || ly >= Hh) continue;
#pragma unroll
            for (int dx = -1; dx <= 1; dx++) {
                int lx = X + dx;
                if (lx < 0 || lx >= Ww) continue;
                int m = tidx[(ly * Ww + lx) * 5 + r];
                int my = m / Ww, mx = m - my * Ww;
                int sy = my - dy, sx = mx - dx;
                if (sy >= 0 && sy < Hh && sx >= 0 && sx < Ww)
                    inner += xT[(sy * Ww + sx) * CIN + c];
            }
        }
        s += S * inner;
    }
    out[c * HW + pix] = feat[c * HW + pix] + x[c * HW + pix] + s * (1.0f / 36.0f);
}

// ---------------------------------------------------------------------------
extern "C" void kernel_launch(void* const* d_in, const int* in_sizes, int n_in,
                              void* d_out, int out_size)
{
    (void)in_sizes; (void)n_in; (void)out_size;
    const float* x  = (const float*)d_in[0];
    const float* W1 = (const float*)d_in[1];
    const float* b1 = (const float*)d_in[2];
    const float* W2 = (const float*)d_in[3];
    const float* b2 = (const float*)d_in[4];
    const float* Wq = (const float*)d_in[5];
    const float* bq = (const float*)d_in[6];
    const float* Wk = (const float*)d_in[7];
    const float* bk = (const float*)d_in[8];
    float* out = (float*)d_out;

    float *t1, *feat, *qb, *kb, *Qn, *Kn, *xT, *tv;
    int* ti;
    cudaGetSymbolAddress((void**)&t1,   g_t1);
    cudaGetSymbolAddress((void**)&feat, g_feat);
    cudaGetSymbolAddress((void**)&qb,   g_q);
    cudaGetSymbolAddress((void**)&kb,   g_k);
    cudaGetSymbolAddress((void**)&Qn,   g_Qn);
    cudaGetSymbolAddress((void**)&Kn,   g_Kn);
    cudaGetSymbolAddress((void**)&xT,   g_xT);
    cudaGetSymbolAddress((void**)&tv,   g_tv);
    cudaGetSymbolAddress((void**)&ti,   g_ti);

    dim3 cblk(32, 8);

    // 64-ch convs: RPT=2, grid 288 (2 CTAs/SM). 32-ch convs: RPT=1, grid 288.
    conv3x3_t<2><<<dim3(3, 6, 16), cblk>>>(x,  W1, b1, t1,   1);
    conv3x3_t<2><<<dim3(3, 6, 16), cblk>>>(t1, W2, b2, feat, 1);
    conv3x3_t<1><<<dim3(3, 12, 8), cblk>>>(x,  Wq, bq, qb,   0);
    conv3x3_t<1><<<dim3(3, 12, 8), cblk>>>(x,  Wk, bk, kb,   0);

    patch_norm_kernel<<<LQ, DQ>>>(qb, Qn);
    patch_norm_kernel<<<LQ, DQ>>>(kb, Kn);
    transpose_x_kernel<<<(CIN * HW + 255) / 256, 256>>>(x, xT);

    sim_top5_kernel<<<144, 256>>>(Kn, Qn, tv, ti);

    assemble_kernel<<<HW / 4, 256>>>(x, xT, feat, tv, ti, out);
}

// round 11
// speedup vs baseline: 2.5278x; 1.8831x over previous
#include <cuda_runtime.h>
#include <cuda_bf16.h>
#include <cstdint>

// ---------------------------------------------------------------------------
// TransformerV2: conv feature branch + patch-similarity top-5 attention.
// Shapes fixed: B=1, Cin=64, Cq=32, H=W=96, L=9216, D=32*9=288.
// R10: similarity GEMM on tensor pipe via baseline-PTX mma.sync bf16
//      (compute_103-safe; tcgen05 rejected by harness PTX target).
//      Exact fp32 rescoring of 32 candidates/query for final top-5.
// ---------------------------------------------------------------------------

#define Hh 96
#define Ww 96
#define HW 9216
#define CIN 64
#define CQ  32
#define DQ  288
#define LQ  9216

typedef unsigned long long ull;

// -------------------------- scratch (static, no allocs) --------------------
__device__ float g_t1  [CIN * HW];
__device__ float g_feat[CIN * HW];
__device__ float g_q   [CQ  * HW];
__device__ float g_k   [CQ  * HW];
__device__ float g_Qn  [LQ * DQ];          // fp32 normalized (for rescore)
__device__ float g_Kn  [LQ * DQ];
__device__ __nv_bfloat16 g_Qnb[LQ * DQ];   // bf16 normalized (for MMA)
__device__ __nv_bfloat16 g_Knb[LQ * DQ];
__device__ float g_xT  [HW * CIN];
__device__ float g_tv  [LQ * 5];
__device__ int   g_ti  [LQ * 5];

// ======================= PTX helpers (compute_103-safe) ====================
__device__ __forceinline__ uint32_t smem_u32(const void* p) {
    uint32_t a;
    asm("{ .reg .u64 t; cvta.to.shared.u64 t, %1; cvt.u32.u64 %0, t; }"
        : "=r"(a) : "l"(p));
    return a;
}
__device__ __forceinline__ void cp16(uint32_t dst, const void* src) {
    asm volatile("cp.async.cg.shared.global [%0], [%1], 16;"
                 :: "r"(dst), "l"(src) : "memory");
}
#define CP_COMMIT() asm volatile("cp.async.commit_group;" ::: "memory")
#define CP_WAIT0()  asm volatile("cp.async.wait_group 0;" ::: "memory")

__device__ __forceinline__ void ldsm4(uint32_t* r, uint32_t addr) {
    asm volatile("ldmatrix.sync.aligned.m8n8.x4.shared.b16 {%0,%1,%2,%3}, [%4];"
                 : "=r"(r[0]), "=r"(r[1]), "=r"(r[2]), "=r"(r[3]) : "r"(addr));
}
__device__ __forceinline__ void mma16816(float* d, const uint32_t* a,
                                         const uint32_t* b) {
    asm volatile(
        "mma.sync.aligned.m16n8k16.row.col.f32.bf16.bf16.f32 "
        "{%0,%1,%2,%3}, {%4,%5,%6,%7}, {%8,%9}, {%0,%1,%2,%3};"
        : "+f"(d[0]), "+f"(d[1]), "+f"(d[2]), "+f"(d[3])
        : "r"(a[0]), "r"(a[1]), "r"(a[2]), "r"(a[3]), "r"(b[0]), "r"(b[1]));
}

// ---------------------------------------------------------------------------
// 3x3 SAME conv (known-good from R8: 4 outs/block, pipelined).
// ---------------------------------------------------------------------------
template<int RPT>
__global__ void __launch_bounds__(256) conv3x3_t(
    const float* __restrict__ in,
    const float* __restrict__ wgt,
    const float* __restrict__ bias,
    float* __restrict__ out,
    int doRelu)
{
    constexpr int TH = 8 * RPT;
    constexpr int TL = (TH + 2) * 34;
    constexpr int NP = (TL + 255) / 256;

    __shared__ float tin[2][TH + 2][36];
    __shared__ float wsm[64][36];

    const int tx = threadIdx.x;
    const int ty = threadIdx.y;
    const int tid = ty * 32 + tx;
    const int x0 = blockIdx.x * 32;
    const int y0 = blockIdx.y * TH;
    const int og = blockIdx.z * 4;

    for (int i = tid; i < 4 * 64 * 9; i += 256) {
        int o = i / 576, rem = i - o * 576, ci = rem / 9, k = rem - ci * 9;
        wsm[ci][o * 9 + k] = wgt[((og + o) * 64 + ci) * 9 + k];
    }

    float pf[NP];
#pragma unroll
    for (int j = 0; j < NP; j++) {
        int i = tid + j * 256;
        float v = 0.f;
        if (i < TL) {
            int r = i / 34, c = i - r * 34;
            int gy = y0 - 1 + r, gx = x0 - 1 + c;
            if (gy >= 0 && gy < Hh && gx >= 0 && gx < Ww)
                v = in[gy * Ww + gx];
        }
        pf[j] = v;
    }

    float acc[4][RPT];
#pragma unroll
    for (int o = 0; o < 4; o++)
#pragma unroll
        for (int rr = 0; rr < RPT; rr++) acc[o][rr] = 0.f;

    for (int ci = 0; ci < 64; ci++) {
        const int buf = ci & 1;
#pragma unroll
        for (int j = 0; j < NP; j++) {
            int i = tid + j * 256;
            if (i < TL) {
                int r = i / 34, c = i - r * 34;
                tin[buf][r][c] = pf[j];
            }
        }
        __syncthreads();

        if (ci < 63) {
            const float* p = in + (ci + 1) * HW;
#pragma unroll
            for (int j = 0; j < NP; j++) {
                int i = tid + j * 256;
                float v = 0.f;
                if (i < TL) {
                    int r = i / 34, c = i - r * 34;
                    int gy = y0 - 1 + r, gx = x0 - 1 + c;
                    if (gy >= 0 && gy < Hh && gx >= 0 && gx < Ww)
                        v = p[gy * Ww + gx];
                }
                pf[j] = v;
            }
        }

        float v[RPT][9];
#pragma unroll
        for (int rr = 0; rr < RPT; rr++) {
            int yl = ty + 8 * rr;
#pragma unroll
            for (int dy = 0; dy < 3; dy++)
#pragma unroll
                for (int dx = 0; dx < 3; dx++)
                    v[rr][dy * 3 + dx] = tin[buf][yl + dy][tx + dx];
        }
#pragma unroll
        for (int o = 0; o < 4; o++) {
            float w9[9];
#pragma unroll
            for (int k = 0; k < 9; k++) w9[k] = wsm[ci][o * 9 + k];
#pragma unroll
            for (int rr = 0; rr < RPT; rr++)
#pragma unroll
                for (int k = 0; k < 9; k++)
                    acc[o][rr] = fmaf(v[rr][k], w9[k], acc[o][rr]);
        }
    }

    const int gx = x0 + tx;
#pragma unroll
    for (int o = 0; o < 4; o++) {
        float b = bias[og + o];
#pragma unroll
        for (int rr = 0; rr < RPT; rr++) {
            int gy = y0 + ty + 8 * rr;
            float r = acc[o][rr] + b;
            if (doRelu) r = fmaxf(r, 0.f);
            out[(og + o) * HW + gy * Ww + gx] = r;
        }
    }
}

// ---------------------------------------------------------------------------
// L2-normalized 3x3 patch vectors, fp32 + bf16 outputs.
// ---------------------------------------------------------------------------
__global__ void patch_norm_kernel(const float* __restrict__ f,
                                  float* __restrict__ vec,
                                  __nv_bfloat16* __restrict__ vecb)
{
    const int l = blockIdx.x;
    const int y = l / Ww, x = l - y * Ww;
    const int d = threadIdx.x;
    const int c = d / 9, ij = d - c * 9;
    const int dy = ij / 3 - 1, dx = ij % 3 - 1;
    const int yy = y + dy, xx = x + dx;

    float v = 0.f;
    if (yy >= 0 && yy < Hh && xx >= 0 && xx < Ww)
        v = f[c * HW + yy * Ww + xx];

    __shared__ float red[9];
    __shared__ float nrm;
    float s = v * v;
#pragma unroll
    for (int off = 16; off > 0; off >>= 1)
        s += __shfl_down_sync(0xffffffffu, s, off);
    if ((d & 31) == 0) red[d >> 5] = s;
    __syncthreads();
    if (d == 0) {
        float t = 0.f;
#pragma unroll
        for (int i = 0; i < 9; i++) t += red[i];
        nrm = fmaxf(sqrtf(t), 1e-12f);
    }
    __syncthreads();
    float o = v / nrm;
    vec[l * DQ + d]  = o;
    vecb[l * DQ + d] = __float2bfloat16(o);
}

// ---------------------------------------------------------------------------
__global__ void transpose_x_kernel(const float* __restrict__ x,
                                   float* __restrict__ xT)
{
    int i = blockIdx.x * 256 + threadIdx.x;
    if (i < CIN * HW) {
        int p = i >> 6, c = i & 63;
        xT[i] = x[c * HW + p];
    }
}

// ---------------------------------------------------------------------------
// mma.sync similarity + streaming top-5 with exact fp32 rescoring.
// CTA: 64 queries, 72 key tiles of 128, K=288 bf16 (18 k-steps of 16).
// 8 warps; warp w computes keys [(w&3)*32,+32) x queries [(w>>2)*32,+32).
// A tiles double-buffered via cp.async; smem row stride 296 bf16 (592 B)
// -> conflict-free ldmatrix (row step = 20 banks, full 8-row cycle).
// grid 144, block 256, dynamic smem 223,232 B.
// ---------------------------------------------------------------------------
#define ASTR   296                         // bf16 elems per smem row
#define ABYTES (128 * ASTR * 2)            // 75776 per A buffer
#define SMB_B  (2 * ABYTES)                // 151552
#define SMB_SC (SMB_B + 64 * ASTR * 2)     // 189440
#define SIM_SMEM (SMB_SC + 128 * 66 * 4)   // 223232

struct SimCand { float v[64][32]; int id[64][32]; };

__global__ void __launch_bounds__(256, 1) sim_top5_mma(
    const __nv_bfloat16* __restrict__ Knb,
    const __nv_bfloat16* __restrict__ Qnb,
    const float* __restrict__ Kn,
    const float* __restrict__ Qn,
    float* __restrict__ tvals,
    int*   __restrict__ tidx)
{
    extern __shared__ __align__(16) char dynsm[];
    const uint32_t smb = smem_u32(dynsm);
    float* scores = (float*)(dynsm + SMB_SC);
    SimCand* cand = (SimCand*)(dynsm + SMB_SC);   // alias (barrier-protected)

    const int tid  = threadIdx.x;
    const int lane = tid & 31;
    const int wid  = tid >> 5;
    const int qBase = blockIdx.x * 64;

    const int wK = (wid & 3) * 32;     // warp's key offset within tile
    const int wQ = (wid >> 2) * 32;    // warp's query offset

    // cp.async staging roles: row = tid>>1, half = tid&1 (144 bf16 each)
    const int sRow = tid >> 1, sHalf = tid & 1;

    // ---- stage B (64 queries x 288) once + preload A tile 0 ----
    if (tid < 128) {
        const __nv_bfloat16* src = Qnb + (qBase + sRow) * DQ + sHalf * 144;
        uint32_t dst = smb + SMB_B + sRow * (ASTR * 2) + sHalf * 288;
#pragma unroll
        for (int j = 0; j < 18; j++) cp16(dst + j * 16, src + j * 8);
    }
    {
        const __nv_bfloat16* src = Knb + sRow * DQ + sHalf * 144;
        uint32_t dst = smb + sRow * (ASTR * 2) + sHalf * 288;
#pragma unroll
        for (int j = 0; j < 18; j++) cp16(dst + j * 16, src + j * 8);
    }
    CP_COMMIT();
    CP_WAIT0();
    __syncthreads();

    // ldmatrix base addresses (byte offsets within buffers)
    // A frag mi: row = wK + mi*16 + (lane&15), k-col byte = ks*32 + (lane>>4)*16
    const uint32_t aOff0 = (uint32_t)(wK + (lane & 15)) * (ASTR * 2)
                         + ((lane >> 4) & 1) * 16;
    const uint32_t aOff1 = aOff0 + 16 * (ASTR * 2);
    // B frag pair: row = wQ + nh*16 + ((lane>>4)&1)*8 + (lane&7),
    //              k-col byte = ks*32 + ((lane>>3)&1)*16
    const uint32_t bRowCom = ((lane >> 4) & 1) * 8 + (lane & 7);
    const uint32_t bOff0 = smb + SMB_B + (uint32_t)(wQ + bRowCom) * (ASTR * 2)
                         + ((lane >> 3) & 1) * 16;
    const uint32_t bOff1 = bOff0 + 16 * (ASTR * 2);

    float v8[8]; int i8[8];
#pragma unroll
    for (int r = 0; r < 8; r++) { v8[r] = -1e30f; i8[r] = 0; }
    const int qScan = tid & 63, span = tid >> 6;

    for (int kt = 0; kt < 72; kt++) {
        const uint32_t aBuf = smb + (uint32_t)(kt & 1) * ABYTES;

        // prefetch next A tile into the other buffer (overlaps compute)
        if (kt < 71) {
            const __nv_bfloat16* src =
                Knb + (size_t)((kt + 1) * 128 + sRow) * DQ + sHalf * 144;
            uint32_t dst = smb + (uint32_t)((kt + 1) & 1) * ABYTES
                         + sRow * (ASTR * 2) + sHalf * 288;
#pragma unroll
            for (int j = 0; j < 18; j++) cp16(dst + j * 16, src + j * 8);
            CP_COMMIT();
        }

        // ---- 32x32 warp-tile GEMM over K=288 ----
        float acc[8][4];
#pragma unroll
        for (int f = 0; f < 8; f++)
#pragma unroll
            for (int e = 0; e < 4; e++) acc[f][e] = 0.f;

#pragma unroll
        for (int ks = 0; ks < 18; ks++) {
            const uint32_t kb = ks * 32;
            uint32_t a0[4], a1[4], b0[4], b1[4];
            ldsm4(a0, aBuf + aOff0 + kb);
            ldsm4(a1, aBuf + aOff1 + kb);
            ldsm4(b0, bOff0 + kb);          // n 0-15 of warp
            ldsm4(b1, bOff1 + kb);          // n 16-31 of warp
            // acc[mi*4+ni]
            mma16816(acc[0], a0, b0);     mma16816(acc[4], a1, b0);
            mma16816(acc[1], a0, b0 + 2); mma16816(acc[5], a1, b0 + 2);
            mma16816(acc[2], a0, b1);     mma16816(acc[6], a1, b1);
            mma16816(acc[3], a0, b1 + 2); mma16816(acc[7], a1, b1 + 2);
        }

        // ---- D frags -> scores[key][query] (stride 66) ----
#pragma unroll
        for (int mi = 0; mi < 2; mi++)
#pragma unroll
            for (int ni = 0; ni < 4; ni++) {
                const float* d = acc[mi * 4 + ni];
                int row = wK + mi * 16 + (lane >> 2);
                int col = wQ + ni * 8 + (lane & 3) * 2;
                *(float2*)&scores[row * 66 + col] = make_float2(d[0], d[1]);
                *(float2*)&scores[(row + 8) * 66 + col] = make_float2(d[2], d[3]);
            }
        __syncthreads();

        // ---- scan: 4 threads/query, 32 keys each, streaming top-8 ----
        {
            const float* col = scores + (span * 32) * 66 + qScan;
            const int gBase = kt * 128 + span * 32;
            for (int i = 0; i < 32; i++) {
                float v = col[i * 66];
                if (v > v8[7]) {
                    v8[7] = v; i8[7] = gBase + i;
#pragma unroll
                    for (int r = 7; r > 0; r--)
                        if (v8[r] > v8[r - 1]) {
                            float tv = v8[r - 1]; v8[r - 1] = v8[r]; v8[r] = tv;
                            int ti = i8[r - 1]; i8[r - 1] = i8[r]; i8[r] = ti;
                        }
                }
            }
        }
        if (kt < 71) CP_WAIT0();
        __syncthreads();   // next A buffer ready; scan done before score STS
    }

    // ---- candidates -> smem (aliases scores; barrier above protects) ----
#pragma unroll
    for (int r = 0; r < 8; r++) {
        cand->v [qScan][span * 8 + r] = v8[r];
        cand->id[qScan][span * 8 + r] = i8[r];
    }
    __syncthreads();

    // ---- exact fp32 rescore: 8 candidates per thread ----
    {
        const float4* qr = (const float4*)(Qn + (size_t)(qBase + qScan) * DQ);
        int ids[8];
#pragma unroll
        for (int j = 0; j < 8; j++) ids[j] = cand->id[qScan][span * 8 + j];
#pragma unroll
        for (int j = 0; j < 8; j++) {
            const float4* kr = (const float4*)(Kn + (size_t)ids[j] * DQ);
            float s = 0.f;
#pragma unroll 4
            for (int t = 0; t < 72; t++) {
                float4 a = qr[t], b = kr[t];
                s += a.x * b.x; s += a.y * b.y; s += a.z * b.z; s += a.w * b.w;
            }
            cand->v[qScan][span * 8 + j] = s;
        }
    }
    __syncthreads();

    // ---- final top-5 selection (tie -> lower index) ----
    if (tid < 64) {
        int q = tid;
        for (int r = 0; r < 5; r++) {
            float best = -1e30f; int bi = 0x7fffffff; int bj = 0;
            for (int j = 0; j < 32; j++) {
                float v = cand->v[q][j]; int id = cand->id[q][j];
                if (v > best || (v == best && id < bi)) { best = v; bi = id; bj = j; }
            }
            tvals[(qBase + q) * 5 + r] = best;
            tidx [(qBase + q) * 5 + r] = bi;
            cand->v[q][bj] = -1e31f;
        }
    }
}

// ---------------------------------------------------------------------------
__global__ void assemble_kernel(const float* __restrict__ x,
                                const float* __restrict__ xT,
                                const float* __restrict__ feat,
                                const float* __restrict__ tvals,
                                const int*   __restrict__ tidx,
                                float* __restrict__ out)
{
    const int tid = threadIdx.x;
    const int pix = blockIdx.x * 4 + (tid >> 6);
    const int c = tid & 63;
    const int Y = pix / Ww, X = pix - Y * Ww;

    float s = 0.f;
#pragma unroll
    for (int r = 1; r < 5; r++) {
        float S = tvals[pix * 5 + r];
        float inner = 0.f;
#pragma unroll
        for (int dy = -1; dy <= 1; dy++) {
            int ly = Y + dy;
            if (ly < 0 || ly >= Hh) continue;
#pragma unroll
            for (int dx = -1; dx <= 1; dx++) {
                int lx = X + dx;
                if (lx < 0 || lx >= Ww) continue;
                int m = tidx[(ly * Ww + lx) * 5 + r];
                int my = m / Ww, mx = m - my * Ww;
                int sy = my - dy, sx = mx - dx;
                if (sy >= 0 && sy < Hh && sx >= 0 && sx < Ww)
                    inner += xT[(sy * Ww + sx) * CIN + c];
            }
        }
        s += S * inner;
    }
    out[c * HW + pix] = feat[c * HW + pix] + x[c * HW + pix] + s * (1.0f / 36.0f);
}

// ---------------------------------------------------------------------------
extern "C" void kernel_launch(void* const* d_in, const int* in_sizes, int n_in,
                              void* d_out, int out_size)
{
    (void)in_sizes; (void)n_in; (void)out_size;
    const float* x  = (const float*)d_in[0];
    const float* W1 = (const float*)d_in[1];
    const float* b1 = (const float*)d_in[2];
    const float* W2 = (const float*)d_in[3];
    const float* b2 = (const float*)d_in[4];
    const float* Wq = (const float*)d_in[5];
    const float* bq = (const float*)d_in[6];
    const float* Wk = (const float*)d_in[7];
    const float* bk = (const float*)d_in[8];
    float* out = (float*)d_out;

    float *t1, *feat, *qb, *kb, *Qn, *Kn, *xT, *tv;
    __nv_bfloat16 *Qnb, *Knb;
    int* ti;
    cudaGetSymbolAddress((void**)&t1,   g_t1);
    cudaGetSymbolAddress((void**)&feat, g_feat);
    cudaGetSymbolAddress((void**)&qb,   g_q);
    cudaGetSymbolAddress((void**)&kb,   g_k);
    cudaGetSymbolAddress((void**)&Qn,   g_Qn);
    cudaGetSymbolAddress((void**)&Kn,   g_Kn);
    cudaGetSymbolAddress((void**)&Qnb,  g_Qnb);
    cudaGetSymbolAddress((void**)&Knb,  g_Knb);
    cudaGetSymbolAddress((void**)&xT,   g_xT);
    cudaGetSymbolAddress((void**)&tv,   g_tv);
    cudaGetSymbolAddress((void**)&ti,   g_ti);

    cudaFuncSetAttribute(sim_top5_mma,
                         cudaFuncAttributeMaxDynamicSharedMemorySize, SIM_SMEM);

    dim3 cblk(32, 8);
    conv3x3_t<2><<<dim3(3, 6, 16), cblk>>>(x,  W1, b1, t1,   1);
    conv3x3_t<2><<<dim3(3, 6, 16), cblk>>>(t1, W2, b2, feat, 1);
    conv3x3_t<1><<<dim3(3, 12, 8), cblk>>>(x,  Wq, bq, qb,   0);
    conv3x3_t<1><<<dim3(3, 12, 8), cblk>>>(x,  Wk, bk, kb,   0);

    patch_norm_kernel<<<LQ, DQ>>>(qb, Qn, Qnb);
    patch_norm_kernel<<<LQ, DQ>>>(kb, Kn, Knb);
    transpose_x_kernel<<<(CIN * HW + 255) / 256, 256>>>(x, xT);

    sim_top5_mma<<<144, 256, SIM_SMEM>>>(Knb, Qnb, Kn, Qn, tv, ti);

    assemble_kernel<<<HW / 4, 256>>>(x, xT, feat, tv, ti, out);
}

// round 12
// speedup vs baseline: 2.5375x; 1.0039x over previous
#include <cuda_runtime.h>
#include <cuda_bf16.h>
#include <cstdint>

// ---------------------------------------------------------------------------
// TransformerV2: conv feature branch + patch-similarity top-5 attention.
// Shapes fixed: B=1, Cin=64, Cq=32, H=W=96, L=9216, D=32*9=288.
// R11: conv rewritten (32ch/barrier staging, cp.async zfill, FFMA2 output
//      pairs, q+k merged). sim (mma.sync bf16 + fp32 rescore) unchanged.
// ---------------------------------------------------------------------------

#define Hh 96
#define Ww 96
#define HW 9216
#define CIN 64
#define CQ  32
#define DQ  288
#define LQ  9216

typedef unsigned long long ull;

// -------------------------- scratch (static, no allocs) --------------------
__device__ float g_t1  [CIN * HW];
__device__ float g_feat[CIN * HW];
__device__ float g_q   [CQ  * HW];
__device__ float g_k   [CQ  * HW];
__device__ float g_Qn  [LQ * DQ];          // fp32 normalized (for rescore)
__device__ float g_Kn  [LQ * DQ];
__device__ __nv_bfloat16 g_Qnb[LQ * DQ];   // bf16 normalized (for MMA)
__device__ __nv_bfloat16 g_Knb[LQ * DQ];
__device__ float g_xT  [HW * CIN];
__device__ float g_tv  [LQ * 5];
__device__ int   g_ti  [LQ * 5];

// ======================= PTX helpers (compute_103-safe) ====================
__device__ __forceinline__ uint32_t smem_u32(const void* p) {
    uint32_t a;
    asm("{ .reg .u64 t; cvta.to.shared.u64 t, %1; cvt.u32.u64 %0, t; }"
        : "=r"(a) : "l"(p));
    return a;
}
__device__ __forceinline__ void cp16(uint32_t dst, const void* src) {
    asm volatile("cp.async.cg.shared.global [%0], [%1], 16;"
                 :: "r"(dst), "l"(src) : "memory");
}
__device__ __forceinline__ void cp4z(uint32_t dst, const void* src, int ok) {
    asm volatile("cp.async.ca.shared.global [%0], [%1], 4, %2;"
                 :: "r"(dst), "l"(src), "r"(ok ? 4 : 0) : "memory");
}
#define CP_COMMIT() asm volatile("cp.async.commit_group;" ::: "memory")
#define CP_WAIT0()  asm volatile("cp.async.wait_group 0;" ::: "memory")

__device__ __forceinline__ void ldsm4(uint32_t* r, uint32_t addr) {
    asm volatile("ldmatrix.sync.aligned.m8n8.x4.shared.b16 {%0,%1,%2,%3}, [%4];"
                 : "=r"(r[0]), "=r"(r[1]), "=r"(r[2]), "=r"(r[3]) : "r"(addr));
}
__device__ __forceinline__ void mma16816(float* d, const uint32_t* a,
                                         const uint32_t* b) {
    asm volatile(
        "mma.sync.aligned.m16n8k16.row.col.f32.bf16.bf16.f32 "
        "{%0,%1,%2,%3}, {%4,%5,%6,%7}, {%8,%9}, {%0,%1,%2,%3};"
        : "+f"(d[0]), "+f"(d[1]), "+f"(d[2]), "+f"(d[3])
        : "r"(a[0]), "r"(a[1]), "r"(a[2]), "r"(a[3]), "r"(b[0]), "r"(b[1]));
}
__device__ __forceinline__ ull fma2(ull a, ull b, ull c) {
    ull d;
    asm("fma.rn.f32x2 %0, %1, %2, %3;" : "=l"(d) : "l"(a), "l"(b), "l"(c));
    return d;
}
__device__ __forceinline__ ull packdup(float v) {
    ull d;
    asm("mov.b64 %0, {%1, %1};" : "=l"(d) : "f"(v));
    return d;
}

// ---------------------------------------------------------------------------
// conv v2: 3x3 SAME, Cin=64. Tile 32(w) x 16(h), 8 output chans per block.
// 32 input channels per barrier stage (2 stages, double-buffered cp.async
// with 4B zero-fill for halo). FFMA2 over output pairs; weights staged as
// interleaved float2 [cin][tap][pair]. Supports two weight sets (merged q+k):
// blockIdx.z < nzA -> set A, else set B.
// grid (3, 6, nzA+nzB), block (32, 8), dynamic smem 175104 B.
// ---------------------------------------------------------------------------
#define CV_TIN   19584                      // 32ch * 18r * 34c floats / stage
#define CV_SMEM  (18432 + 2 * CV_TIN * 4)   // wpair + 2 tin buffers = 175104

__global__ void __launch_bounds__(256, 1) conv_v2(
    const float* __restrict__ in,
    const float* __restrict__ wA, const float* __restrict__ bA,
    float* __restrict__ outA,
    const float* __restrict__ wB, const float* __restrict__ bB,
    float* __restrict__ outB,
    int nzA, int doRelu)
{
    extern __shared__ __align__(16) char dynsm[];
    float2* wp  = (float2*)dynsm;                 // [64][9][4] float2
    float*  tin = (float*)(dynsm + 18432);        // [2][32][18][34]

    const int tx = threadIdx.x;
    const int ty = threadIdx.y;
    const int tid = ty * 32 + tx;
    const int x0 = blockIdx.x * 32;
    const int y0 = blockIdx.y * 16;
    const int zi = blockIdx.z;
    const bool isA = (zi < nzA);
    const int og = (isA ? zi : zi - nzA) * 8;
    const float* wgt  = isA ? wA : wB;
    const float* bias = isA ? bA : bB;
    float* out        = isA ? outA : outB;

    // stage weights as output-pair float2: wp[ci*36 + k*4 + p]
    for (int i = tid; i < 2304; i += 256) {
        int ci = i / 36, rem = i - ci * 36, k = rem >> 2, p = rem & 3;
        int o0 = og + 2 * p;
        float2 w;
        w.x = wgt[(o0 * 64 + ci) * 9 + k];
        w.y = wgt[((o0 + 1) * 64 + ci) * 9 + k];
        wp[i] = w;
    }

    // async stage loader: 32 channels (stage*32..+32), rows y0-1..y0+16,
    // cols x0-1..x0+32, zero-filled out of bounds.
    auto stage_load = [&](int buf, int stage) {
        const float* base = in + stage * 32 * HW;
        float* db = tin + buf * CV_TIN;
#pragma unroll 1
        for (int j = 0; j < 77; j++) {
            int i = tid + j * 256;
            if (i < CV_TIN) {
                int ch = i / 612, rem = i - ch * 612;
                int r = rem / 34, c = rem - r * 34;
                int gy = y0 - 1 + r, gx = x0 - 1 + c;
                bool ok = (gy >= 0 && gy < Hh && gx >= 0 && gx < Ww);
                const float* src = ok ? (base + ch * HW + gy * Ww + gx) : base;
                cp4z(smem_u32(db + i), src, ok);
            }
        }
    };

    stage_load(0, 0);
    CP_COMMIT();

    ull acc2[4][2];
#pragma unroll
    for (int p = 0; p < 4; p++) { acc2[p][0] = 0ull; acc2[p][1] = 0ull; }

#pragma unroll 1
    for (int stage = 0; stage < 2; stage++) {
        CP_WAIT0();
        __syncthreads();
        if (stage == 0) { stage_load(1, 1); CP_COMMIT(); }

        const float* tb = tin + stage * CV_TIN;
        const ull* wbase = (const ull*)(wp + stage * 32 * 36);
#pragma unroll 2
        for (int ci = 0; ci < 32; ci++) {
            const float* tci = tb + ci * 612;
            const ull* wrow = wbase + ci * 36;
#pragma unroll
            for (int k = 0; k < 9; k++) {
                const int dy = k / 3, dx = k - dy * 3;
                ull v0 = packdup(tci[(ty + dy) * 34 + tx + dx]);
                ull v1 = packdup(tci[(ty + 8 + dy) * 34 + tx + dx]);
#pragma unroll
                for (int p = 0; p < 4; p++) {
                    ull w2 = wrow[k * 4 + p];
                    acc2[p][0] = fma2(w2, v0, acc2[p][0]);
                    acc2[p][1] = fma2(w2, v1, acc2[p][1]);
                }
            }
        }
    }

    // write out: pairs (og+2p, og+2p+1), rows ty and ty+8
#pragma unroll
    for (int p = 0; p < 4; p++) {
        int o0 = og + 2 * p;
        float b0 = bias[o0], b1 = bias[o0 + 1];
#pragma unroll
        for (int rr = 0; rr < 2; rr++) {
            float2 a = *(float2*)&acc2[p][rr];
            int gy = y0 + ty + 8 * rr;
            float r0 = a.x + b0, r1 = a.y + b1;
            if (doRelu) { r0 = fmaxf(r0, 0.f); r1 = fmaxf(r1, 0.f); }
            out[o0 * HW + gy * Ww + x0 + tx] = r0;
            out[(o0 + 1) * HW + gy * Ww + x0 + tx] = r1;
        }
    }
}

// ---------------------------------------------------------------------------
// L2-normalized 3x3 patch vectors, fp32 + bf16 outputs. q and k in one
// launch: blockIdx.y = 0 -> q, 1 -> k. grid (9216, 2), block 288.
// ---------------------------------------------------------------------------
__global__ void patch_norm_kernel(
    const float* __restrict__ fq, const float* __restrict__ fk,
    float* __restrict__ vq, __nv_bfloat16* __restrict__ vqb,
    float* __restrict__ vk, __nv_bfloat16* __restrict__ vkb)
{
    const float* f = blockIdx.y ? fk : fq;
    float* vec = blockIdx.y ? vk : vq;
    __nv_bfloat16* vecb = blockIdx.y ? vkb : vqb;

    const int l = blockIdx.x;
    const int y = l / Ww, x = l - y * Ww;
    const int d = threadIdx.x;
    const int c = d / 9, ij = d - c * 9;
    const int dy = ij / 3 - 1, dx = ij % 3 - 1;
    const int yy = y + dy, xx = x + dx;

    float v = 0.f;
    if (yy >= 0 && yy < Hh && xx >= 0 && xx < Ww)
        v = f[c * HW + yy * Ww + xx];

    __shared__ float red[9];
    __shared__ float nrm;
    float s = v * v;
#pragma unroll
    for (int off = 16; off > 0; off >>= 1)
        s += __shfl_down_sync(0xffffffffu, s, off);
    if ((d & 31) == 0) red[d >> 5] = s;
    __syncthreads();
    if (d == 0) {
        float t = 0.f;
#pragma unroll
        for (int i = 0; i < 9; i++) t += red[i];
        nrm = fmaxf(sqrtf(t), 1e-12f);
    }
    __syncthreads();
    float o = v / nrm;
    vec[l * DQ + d]  = o;
    vecb[l * DQ + d] = __float2bfloat16(o);
}

// ---------------------------------------------------------------------------
__global__ void transpose_x_kernel(const float* __restrict__ x,
                                   float* __restrict__ xT)
{
    int i = blockIdx.x * 256 + threadIdx.x;
    if (i < CIN * HW) {
        int p = i >> 6, c = i & 63;
        xT[i] = x[c * HW + p];
    }
}

// ---------------------------------------------------------------------------
// mma.sync similarity + streaming top-5 with exact fp32 rescoring.
// (unchanged from R10 — measured ~85% of the legacy-HMMA issue ceiling)
// ---------------------------------------------------------------------------
#define ASTR   296                         // bf16 elems per smem row
#define ABYTES (128 * ASTR * 2)            // 75776 per A buffer
#define SMB_B  (2 * ABYTES)                // 151552
#define SMB_SC (SMB_B + 64 * ASTR * 2)     // 189440
#define SIM_SMEM (SMB_SC + 128 * 66 * 4)   // 223232

struct SimCand { float v[64][32]; int id[64][32]; };

__global__ void __launch_bounds__(256, 1) sim_top5_mma(
    const __nv_bfloat16* __restrict__ Knb,
    const __nv_bfloat16* __restrict__ Qnb,
    const float* __restrict__ Kn,
    const float* __restrict__ Qn,
    float* __restrict__ tvals,
    int*   __restrict__ tidx)
{
    extern __shared__ __align__(16) char dynsm[];
    const uint32_t smb = smem_u32(dynsm);
    float* scores = (float*)(dynsm + SMB_SC);
    SimCand* cand = (SimCand*)(dynsm + SMB_SC);   // alias (barrier-protected)

    const int tid  = threadIdx.x;
    const int lane = tid & 31;
    const int wid  = tid >> 5;
    const int qBase = blockIdx.x * 64;

    const int wK = (wid & 3) * 32;     // warp's key offset within tile
    const int wQ = (wid >> 2) * 32;    // warp's query offset

    const int sRow = tid >> 1, sHalf = tid & 1;

    // ---- stage B (64 queries x 288) once + preload A tile 0 ----
    if (tid < 128) {
        const __nv_bfloat16* src = Qnb + (qBase + sRow) * DQ + sHalf * 144;
        uint32_t dst = smb + SMB_B + sRow * (ASTR * 2) + sHalf * 288;
#pragma unroll
        for (int j = 0; j < 18; j++) cp16(dst + j * 16, src + j * 8);
    }
    {
        const __nv_bfloat16* src = Knb + sRow * DQ + sHalf * 144;
        uint32_t dst = smb + sRow * (ASTR * 2) + sHalf * 288;
#pragma unroll
        for (int j = 0; j < 18; j++) cp16(dst + j * 16, src + j * 8);
    }
    CP_COMMIT();
    CP_WAIT0();
    __syncthreads();

    const uint32_t aOff0 = (uint32_t)(wK + (lane & 15)) * (ASTR * 2)
                         + ((lane >> 4) & 1) * 16;
    const uint32_t aOff1 = aOff0 + 16 * (ASTR * 2);
    const uint32_t bRowCom = ((lane >> 4) & 1) * 8 + (lane & 7);
    const uint32_t bOff0 = smb + SMB_B + (uint32_t)(wQ + bRowCom) * (ASTR * 2)
                         + ((lane >> 3) & 1) * 16;
    const uint32_t bOff1 = bOff0 + 16 * (ASTR * 2);

    float v8[8]; int i8[8];
#pragma unroll
    for (int r = 0; r < 8; r++) { v8[r] = -1e30f; i8[r] = 0; }
    const int qScan = tid & 63, span = tid >> 6;

    for (int kt = 0; kt < 72; kt++) {
        const uint32_t aBuf = smb + (uint32_t)(kt & 1) * ABYTES;

        if (kt < 71) {
            const __nv_bfloat16* src =
                Knb + (size_t)((kt + 1) * 128 + sRow) * DQ + sHalf * 144;
            uint32_t dst = smb + (uint32_t)((kt + 1) & 1) * ABYTES
                         + sRow * (ASTR * 2) + sHalf * 288;
#pragma unroll
            for (int j = 0; j < 18; j++) cp16(dst + j * 16, src + j * 8);
            CP_COMMIT();
        }

        float acc[8][4];
#pragma unroll
        for (int f = 0; f < 8; f++)
#pragma unroll
            for (int e = 0; e < 4; e++) acc[f][e] = 0.f;

#pragma unroll
        for (int ks = 0; ks < 18; ks++) {
            const uint32_t kb = ks * 32;
            uint32_t a0[4], a1[4], b0[4], b1[4];
            ldsm4(a0, aBuf + aOff0 + kb);
            ldsm4(a1, aBuf + aOff1 + kb);
            ldsm4(b0, bOff0 + kb);
            ldsm4(b1, bOff1 + kb);
            mma16816(acc[0], a0, b0);     mma16816(acc[4], a1, b0);
            mma16816(acc[1], a0, b0 + 2); mma16816(acc[5], a1, b0 + 2);
            mma16816(acc[2], a0, b1);     mma16816(acc[6], a1, b1);
            mma16816(acc[3], a0, b1 + 2); mma16816(acc[7], a1, b1 + 2);
        }

#pragma unroll
        for (int mi = 0; mi < 2; mi++)
#pragma unroll
            for (int ni = 0; ni < 4; ni++) {
                const float* d = acc[mi * 4 + ni];
                int row = wK + mi * 16 + (lane >> 2);
                int col = wQ + ni * 8 + (lane & 3) * 2;
                *(float2*)&scores[row * 66 + col] = make_float2(d[0], d[1]);
                *(float2*)&scores[(row + 8) * 66 + col] = make_float2(d[2], d[3]);
            }
        __syncthreads();

        {
            const float* col = scores + (span * 32) * 66 + qScan;
            const int gBase = kt * 128 + span * 32;
            for (int i = 0; i < 32; i++) {
                float v = col[i * 66];
                if (v > v8[7]) {
                    v8[7] = v; i8[7] = gBase + i;
#pragma unroll
                    for (int r = 7; r > 0; r--)
                        if (v8[r] > v8[r - 1]) {
                            float tv = v8[r - 1]; v8[r - 1] = v8[r]; v8[r] = tv;
                            int ti = i8[r - 1]; i8[r - 1] = i8[r]; i8[r] = ti;
                        }
                }
            }
        }
        if (kt < 71) CP_WAIT0();
        __syncthreads();
    }

#pragma unroll
    for (int r = 0; r < 8; r++) {
        cand->v [qScan][span * 8 + r] = v8[r];
        cand->id[qScan][span * 8 + r] = i8[r];
    }
    __syncthreads();

    {
        const float4* qr = (const float4*)(Qn + (size_t)(qBase + qScan) * DQ);
        int ids[8];
#pragma unroll
        for (int j = 0; j < 8; j++) ids[j] = cand->id[qScan][span * 8 + j];
#pragma unroll
        for (int j = 0; j < 8; j++) {
            const float4* kr = (const float4*)(Kn + (size_t)ids[j] * DQ);
            float s = 0.f;
#pragma unroll 4
            for (int t = 0; t < 72; t++) {
                float4 a = qr[t], b = kr[t];
                s += a.x * b.x; s += a.y * b.y; s += a.z * b.z; s += a.w * b.w;
            }
            cand->v[qScan][span * 8 + j] = s;
        }
    }
    __syncthreads();

    if (tid < 64) {
        int q = tid;
        for (int r = 0; r < 5; r++) {
            float best = -1e30f; int bi = 0x7fffffff; int bj = 0;
            for (int j = 0; j < 32; j++) {
                float v = cand->v[q][j]; int id = cand->id[q][j];
                if (v > best || (v == best && id < bi)) { best = v; bi = id; bj = j; }
            }
            tvals[(qBase + q) * 5 + r] = best;
            tidx [(qBase + q) * 5 + r] = bi;
            cand->v[q][bj] = -1e31f;
        }
    }
}

// ---------------------------------------------------------------------------
__global__ void assemble_kernel(const float* __restrict__ x,
                                const float* __restrict__ xT,
                                const float* __restrict__ feat,
                                const float* __restrict__ tvals,
                                const int*   __restrict__ tidx,
                                float* __restrict__ out)
{
    const int tid = threadIdx.x;
    const int pix = blockIdx.x * 4 + (tid >> 6);
    const int c = tid & 63;
    const int Y = pix / Ww, X = pix - Y * Ww;

    float s = 0.f;
#pragma unroll
    for (int r = 1; r < 5; r++) {
        float S = tvals[pix * 5 + r];
        float inner = 0.f;
#pragma unroll
        for (int dy = -1; dy <= 1; dy++) {
            int ly = Y + dy;
            if (ly < 0 || ly >= Hh) continue;
#pragma unroll
            for (int dx = -1; dx <= 1; dx++) {
                int lx = X + dx;
                if (lx < 0 || lx >= Ww) continue;
                int m = tidx[(ly * Ww + lx) * 5 + r];
                int my = m / Ww, mx = m - my * Ww;
                int sy = my - dy, sx = mx - dx;
                if (sy >= 0 && sy < Hh && sx >= 0 && sx < Ww)
                    inner += xT[(sy * Ww + sx) * CIN + c];
            }
        }
        s += S * inner;
    }
    out[c * HW + pix] = feat[c * HW + pix] + x[c * HW + pix] + s * (1.0f / 36.0f);
}

// ---------------------------------------------------------------------------
extern "C" void kernel_launch(void* const* d_in, const int* in_sizes, int n_in,
                              void* d_out, int out_size)
{
    (void)in_sizes; (void)n_in; (void)out_size;
    const float* x  = (const float*)d_in[0];
    const float* W1 = (const float*)d_in[1];
    const float* b1 = (const float*)d_in[2];
    const float* W2 = (const float*)d_in[3];
    const float* b2 = (const float*)d_in[4];
    const float* Wq = (const float*)d_in[5];
    const float* bq = (const float*)d_in[6];
    const float* Wk = (const float*)d_in[7];
    const float* bk = (const float*)d_in[8];
    float* out = (float*)d_out;

    float *t1, *feat, *qb, *kb, *Qn, *Kn, *xT, *tv;
    __nv_bfloat16 *Qnb, *Knb;
    int* ti;
    cudaGetSymbolAddress((void**)&t1,   g_t1);
    cudaGetSymbolAddress((void**)&feat, g_feat);
    cudaGetSymbolAddress((void**)&qb,   g_q);
    cudaGetSymbolAddress((void**)&kb,   g_k);
    cudaGetSymbolAddress((void**)&Qn,   g_Qn);
    cudaGetSymbolAddress((void**)&Kn,   g_Kn);
    cudaGetSymbolAddress((void**)&Qnb,  g_Qnb);
    cudaGetSymbolAddress((void**)&Knb,  g_Knb);
    cudaGetSymbolAddress((void**)&xT,   g_xT);
    cudaGetSymbolAddress((void**)&tv,   g_tv);
    cudaGetSymbolAddress((void**)&ti,   g_ti);

    cudaFuncSetAttribute(conv_v2,
                         cudaFuncAttributeMaxDynamicSharedMemorySize, CV_SMEM);
    cudaFuncSetAttribute(sim_top5_mma,
                         cudaFuncAttributeMaxDynamicSharedMemorySize, SIM_SMEM);

    dim3 cblk(32, 8);
    // merged q+k conv: z 0..3 -> Wq, 4..7 -> Wk
    conv_v2<<<dim3(3, 6, 8), cblk, CV_SMEM>>>(x, Wq, bq, qb, Wk, bk, kb, 4, 0);
    // feature branch convs (relu)
    conv_v2<<<dim3(3, 6, 8), cblk, CV_SMEM>>>(x,  W1, b1, t1,  W1, b1, t1, 8, 1);
    conv_v2<<<dim3(3, 6, 8), cblk, CV_SMEM>>>(t1, W2, b2, feat, W2, b2, feat, 8, 1);

    patch_norm_kernel<<<dim3(LQ, 2), DQ>>>(qb, kb, Qn, Qnb, Kn, Knb);
    transpose_x_kernel<<<(CIN * HW + 255) / 256, 256>>>(x, xT);

    sim_top5_mma<<<144, 256, SIM_SMEM>>>(Knb, Qnb, Kn, Qn, tv, ti);

    assemble_kernel<<<HW / 4, 256>>>(x, xT, feat, tv, ti, out);
}